// round 2
// baseline (speedup 1.0000x reference)
#include <cuda_runtime.h>
#include <cuda_bf16.h>
#include <math.h>

// Problem dims
#define Bc 4096
#define Tc 128
#define Vc 30
#define Ec 256
#define Hc 128
#define Gc 512      // 4*H gates
#define NBLK 32     // batch rows per block
#define NTHR 512

// Scratch (no cudaMalloc allowed)
__device__ float  d_EW[Vc * Gc];   // precomputed x-side gates per vocab id
__device__ double d_loss_sum;
__device__ double d_mask_sum;

__global__ void zero_kernel() {
    d_loss_sum = 0.0;
    d_mask_sum = 0.0;
}

// EW[v][j] = b_ih[j] + b_hh[j] + sum_e W_ih[j][e] * emb[v][e]
__global__ void ew_kernel(const float* __restrict__ emb,
                          const float* __restrict__ W_ih,
                          const float* __restrict__ b_ih,
                          const float* __restrict__ b_hh) {
    __shared__ float ev[Ec];
    int v = blockIdx.x;
    int j = threadIdx.x;
    for (int e = threadIdx.x; e < Ec; e += blockDim.x) ev[e] = emb[v * Ec + e];
    __syncthreads();
    float s = b_ih[j] + b_hh[j];
    const float* w = W_ih + j * Ec;
#pragma unroll 8
    for (int e = 0; e < Ec; e++) s += w[e] * ev[e];
    d_EW[v * Gc + j] = s;
}

__global__ void mask_sum_kernel(const float* __restrict__ mask, int n) {
    double local = 0.0;
    for (int i = blockIdx.x * blockDim.x + threadIdx.x; i < n;
         i += gridDim.x * blockDim.x)
        local += (double)mask[i];
#pragma unroll
    for (int o = 16; o; o >>= 1) local += __shfl_down_sync(0xffffffffu, local, o);
    __shared__ double ws[32];
    int lane = threadIdx.x & 31, w = threadIdx.x >> 5;
    if (lane == 0) ws[w] = local;
    __syncthreads();
    if (w == 0) {
        local = (lane < (int)(blockDim.x >> 5)) ? ws[lane] : 0.0;
#pragma unroll
        for (int o = 16; o; o >>= 1) local += __shfl_down_sync(0xffffffffu, local, o);
        if (lane == 0) atomicAdd(&d_mask_sum, local);
    }
}

// Main recurrent kernel. One CTA owns NBLK=32 batch rows for all 127 steps.
// SMEM: W_hh as bf16x2 (k-major), h[32][128] fp32, W_lin (k-major, padded to 32 v).
// Thread tid: hidden unit u = tid&127, batch group bgrp = tid>>7 (8 rows each).
// Each thread computes all 4 gates for (u, 8 batch rows); c lives in registers.
__global__ void __launch_bounds__(NTHR, 1)
lstm_kernel(const int* __restrict__ inpt,
            const float* __restrict__ h0,
            const float* __restrict__ c0,
            const float* __restrict__ mask,
            const float* __restrict__ W_hh,
            const float* __restrict__ W_lin,
            const float* __restrict__ b_lin) {
    extern __shared__ char smem[];
    __nv_bfloat162* whh2 = (__nv_bfloat162*)smem;                 // [64][512]
    float* h_s = (float*)(smem + 64 * Gc * sizeof(__nv_bfloat162)); // [32][128]
    float* wl  = h_s + NBLK * Hc;                                  // [128][32]
    float* bl  = wl + Hc * 32;                                     // [32]

    const int tid  = threadIdx.x;
    const int lane = tid & 31;
    const int warp = tid >> 5;
    const int u    = tid & 127;
    const int bgrp = tid >> 7;          // 0..3 (constant within a warp)
    const int b0   = blockIdx.x * NBLK;

    // Load W_hh -> bf16x2, k-major: whh2[kk][j] = (W[j][2kk], W[j][2kk+1])
    for (int idx = tid; idx < Gc * 64; idx += NTHR) {
        int j  = idx & (Gc - 1);
        int kk = idx >> 9;
        float2 wv = *(const float2*)&W_hh[j * Hc + 2 * kk];
        whh2[kk * Gc + j] = __floats2bfloat162_rn(wv.x, wv.y);
    }
    // W_lin k-major, v padded to 32 (pad entries zeroed)
    for (int idx = tid; idx < Hc * 32; idx += NTHR) wl[idx] = 0.f;
    __syncthreads();
    for (int idx = tid; idx < Vc * Hc; idx += NTHR) {
        int v = idx / Hc, k = idx % Hc;
        wl[k * 32 + v] = W_lin[idx];
    }
    if (tid < 32) bl[tid] = (tid < Vc) ? b_lin[tid] : 0.f;

    for (int idx = tid; idx < NBLK * Hc; idx += NTHR)
        h_s[idx] = h0[b0 * Hc + idx];

    float c_reg[8];
#pragma unroll
    for (int i = 0; i < 8; i++)
        c_reg[i] = c0[(b0 + bgrp * 8 + i) * Hc + u];

    float my_loss = 0.f;
    __syncthreads();

    for (int t = 0; t < Tc - 1; t++) {
        // ---- gates = EW[token] + h @ W_hh^T ----
        float acc[4][8];
#pragma unroll
        for (int i = 0; i < 8; i++) {
            int tk = inpt[(b0 + bgrp * 8 + i) * Tc + t];
            const float* er = d_EW + tk * Gc;
            acc[0][i] = er[u];
            acc[1][i] = er[u + 128];
            acc[2][i] = er[u + 256];
            acc[3][i] = er[u + 384];
        }
#pragma unroll 2
        for (int kk = 0; kk < 64; kk++) {
            float2 w0 = __bfloat1622float2(whh2[kk * Gc + u]);
            float2 w1 = __bfloat1622float2(whh2[kk * Gc + u + 128]);
            float2 w2 = __bfloat1622float2(whh2[kk * Gc + u + 256]);
            float2 w3 = __bfloat1622float2(whh2[kk * Gc + u + 384]);
#pragma unroll
            for (int i = 0; i < 8; i++) {
                float2 hb = *(const float2*)&h_s[(bgrp * 8 + i) * Hc + 2 * kk];
                acc[0][i] += w0.x * hb.x; acc[0][i] += w0.y * hb.y;
                acc[1][i] += w1.x * hb.x; acc[1][i] += w1.y * hb.y;
                acc[2][i] += w2.x * hb.x; acc[2][i] += w2.y * hb.y;
                acc[3][i] += w3.x * hb.x; acc[3][i] += w3.y * hb.y;
            }
        }
        // ---- LSTM cell (c in registers) ----
        float h2v[8];
#pragma unroll
        for (int i = 0; i < 8; i++) {
            float ig = 1.f / (1.f + expf(-acc[0][i]));
            float fg = 1.f / (1.f + expf(-acc[1][i]));
            float gg = tanhf(acc[2][i]);
            float og = 1.f / (1.f + expf(-acc[3][i]));
            float c2 = fg * c_reg[i] + ig * gg;
            c_reg[i] = c2;
            h2v[i] = og * tanhf(c2);
        }
        __syncthreads();   // everyone done reading old h_s
#pragma unroll
        for (int i = 0; i < 8; i++)
            h_s[(bgrp * 8 + i) * Hc + u] = h2v[i];
        __syncthreads();   // new h visible

        // ---- logits + log-softmax CE: one warp handles 2 batch rows ----
#pragma unroll
        for (int bi = 0; bi < 2; bi++) {
            int brow = warp * 2 + bi;
            float logit = (lane < Vc) ? bl[lane] : -INFINITY;
            const float* hrow = &h_s[brow * Hc];
#pragma unroll 4
            for (int k4 = 0; k4 < 32; k4++) {
                float4 hv = *(const float4*)&hrow[4 * k4];
                float wv0 = wl[(4 * k4 + 0) * 32 + lane];
                float wv1 = wl[(4 * k4 + 1) * 32 + lane];
                float wv2 = wl[(4 * k4 + 2) * 32 + lane];
                float wv3 = wl[(4 * k4 + 3) * 32 + lane];
                logit += hv.x * wv0 + hv.y * wv1 + hv.z * wv2 + hv.w * wv3;
            }
            float mx = logit;
#pragma unroll
            for (int o = 16; o; o >>= 1)
                mx = fmaxf(mx, __shfl_xor_sync(0xffffffffu, mx, o));
            float ex = (lane < Vc) ? expf(logit - mx) : 0.f;
            float sum = ex;
#pragma unroll
            for (int o = 16; o; o >>= 1)
                sum += __shfl_xor_sync(0xffffffffu, sum, o);
            int y = inpt[(b0 + brow) * Tc + t + 1];
            float ly = __shfl_sync(0xffffffffu, logit, y);
            if (lane == 0) {
                float m = mask[(b0 + brow) * Tc + t];
                my_loss += (mx + logf(sum) - ly) * m;
            }
        }
    }

    // block-reduce loss, one atomic per block
#pragma unroll
    for (int o = 16; o; o >>= 1)
        my_loss += __shfl_xor_sync(0xffffffffu, my_loss, o);
    __shared__ float wsum[16];
    if (lane == 0) wsum[warp] = my_loss;
    __syncthreads();
    if (warp == 0) {
        float v = (lane < 16) ? wsum[lane] : 0.f;
#pragma unroll
        for (int o = 8; o; o >>= 1)
            v += __shfl_xor_sync(0xffffffffu, v, o);
        if (lane == 0) atomicAdd(&d_loss_sum, (double)v);
    }
}

__global__ void finalize_kernel(float* out) {
    out[0] = (float)(d_loss_sum / d_mask_sum);
}

extern "C" void kernel_launch(void* const* d_in, const int* in_sizes, int n_in,
                              void* d_out, int out_size) {
    const int*   inpt  = (const int*)d_in[0];
    const float* h0    = (const float*)d_in[1];
    const float* c0    = (const float*)d_in[2];
    const float* mask  = (const float*)d_in[3];
    // d_in[4] = beta (unused by reference)
    const float* emb   = (const float*)d_in[5];
    const float* W_ih  = (const float*)d_in[6];
    const float* b_ih  = (const float*)d_in[7];
    const float* W_hh  = (const float*)d_in[8];
    const float* b_hh  = (const float*)d_in[9];
    const float* W_lin = (const float*)d_in[10];
    const float* b_lin = (const float*)d_in[11];
    float* out = (float*)d_out;

    const size_t smem_main = 64 * Gc * sizeof(__nv_bfloat162)  // 131072
                           + NBLK * Hc * sizeof(float)          // 16384
                           + Hc * 32 * sizeof(float)            // 16384
                           + 32 * sizeof(float);                // 128
    cudaFuncSetAttribute(lstm_kernel,
                         cudaFuncAttributeMaxDynamicSharedMemorySize,
                         (int)smem_main);

    zero_kernel<<<1, 1>>>();
    mask_sum_kernel<<<256, 256>>>(mask, Bc * Tc);
    ew_kernel<<<Vc, Gc>>>(emb, W_ih, b_ih, b_hh);
    lstm_kernel<<<Bc / NBLK, NTHR, smem_main>>>(inpt, h0, c0, mask,
                                                W_hh, W_lin, b_lin);
    finalize_kernel<<<1, 1>>>(out);
}

// round 3
// speedup vs baseline: 7.3989x; 7.3989x over previous
#include <cuda_runtime.h>
#include <cuda_bf16.h>
#include <math.h>
#include <stdint.h>

// Problem dims
#define Bc 4096
#define Tc 128
#define Vc 30
#define Ec 256
#define Hc 128
#define Gc 512      // 4*H
#define NBLK 32     // batch rows per CTA
#define NTHR 512    // 16 warps
#define PITCH 136   // bf16 elements per row (272B) -> conflict-free ldmatrix

// Scratch
__device__ float  d_EW[Vc * Gc];   // x-side gate table, PERMUTED g' = 4u + j
__device__ double d_loss_sum;
__device__ double d_mask_sum;

__global__ void zero_kernel() { d_loss_sum = 0.0; d_mask_sum = 0.0; }

// EW'[v][gp], gp = 4u+j, g = j*128+u
__global__ void ew_kernel(const float* __restrict__ emb,
                          const float* __restrict__ W_ih,
                          const float* __restrict__ b_ih,
                          const float* __restrict__ b_hh) {
    __shared__ float ev[Ec];
    int v = blockIdx.x;
    int gp = threadIdx.x;
    int g = (gp & 3) * Hc + (gp >> 2);
    for (int e = threadIdx.x; e < Ec; e += blockDim.x) ev[e] = emb[v * Ec + e];
    __syncthreads();
    float s = b_ih[g] + b_hh[g];
    const float* w = W_ih + g * Ec;
#pragma unroll 8
    for (int e = 0; e < Ec; e++) s += w[e] * ev[e];
    d_EW[v * Gc + gp] = s;
}

__global__ void mask_sum_kernel(const float* __restrict__ mask, int n) {
    double local = 0.0;
    for (int i = blockIdx.x * blockDim.x + threadIdx.x; i < n;
         i += gridDim.x * blockDim.x)
        local += (double)mask[i];
#pragma unroll
    for (int o = 16; o; o >>= 1) local += __shfl_down_sync(0xffffffffu, local, o);
    __shared__ double ws[32];
    int lane = threadIdx.x & 31, w = threadIdx.x >> 5;
    if (lane == 0) ws[w] = local;
    __syncthreads();
    if (w == 0) {
        local = (lane < (int)(blockDim.x >> 5)) ? ws[lane] : 0.0;
#pragma unroll
        for (int o = 16; o; o >>= 1) local += __shfl_down_sync(0xffffffffu, local, o);
        if (lane == 0) atomicAdd(&d_mask_sum, local);
    }
}

__device__ __forceinline__ uint32_t s2u(const void* p) {
    return (uint32_t)__cvta_generic_to_shared(p);
}
__device__ __forceinline__ float tanhapx(float x) {
    float y; asm("tanh.approx.f32 %0, %1;" : "=f"(y) : "f"(x)); return y;
}
__device__ __forceinline__ float sigapx(float x) {
    return fmaf(tanhapx(0.5f * x), 0.5f, 0.5f);
}

#define LDSM4(R, ADDR) \
    asm volatile("ldmatrix.sync.aligned.m8n8.x4.shared.b16 {%0,%1,%2,%3},[%4];" \
        : "=r"(R[0]),"=r"(R[1]),"=r"(R[2]),"=r"(R[3]) : "r"(ADDR))

#define MMAB(D, A, b0, b1) \
    asm volatile("mma.sync.aligned.m16n8k16.row.col.f32.bf16.bf16.f32 " \
        "{%0,%1,%2,%3},{%4,%5,%6,%7},{%8,%9},{%0,%1,%2,%3};" \
        : "+f"(D[0]),"+f"(D[1]),"+f"(D[2]),"+f"(D[3]) \
        : "r"(A[0]),"r"(A[1]),"r"(A[2]),"r"(A[3]),"r"(b0),"r"(b1))

// SMEM layout (bytes)
#define SM_WHH   0                                   // bf16 [512][PITCH]   139264
#define SM_H     (SM_WHH + Gc * PITCH * 2)           // bf16 [32][PITCH]      8704
#define SM_WL    (SM_H + NBLK * PITCH * 2)           // bf16 [32][PITCH]      8704
#define SM_EW    (SM_WL + 32 * PITCH * 2)            // f32  [30][512]       61440
#define SM_LOG   (SM_EW + Vc * Gc * 4)               // f32  [32][36]         4608
#define SM_BL    (SM_LOG + 32 * 36 * 4)              // f32  [32]              128
#define SM_TOK   (SM_BL + 32 * 4)                    // u8   [32][128]        4096
#define SM_TOTAL (SM_TOK + NBLK * Tc)                //                     226944

__global__ void __launch_bounds__(NTHR, 1)
lstm_kernel(const int* __restrict__ inpt,
            const float* __restrict__ h0,
            const float* __restrict__ c0,
            const float* __restrict__ mask,
            const float* __restrict__ W_hh,
            const float* __restrict__ W_lin,
            const float* __restrict__ b_lin) {
    extern __shared__ char smem[];
    __nv_bfloat16* whh_s = (__nv_bfloat16*)(smem + SM_WHH);
    __nv_bfloat16* h_s   = (__nv_bfloat16*)(smem + SM_H);
    __nv_bfloat16* wl_s  = (__nv_bfloat16*)(smem + SM_WL);
    float*         ew_s  = (float*)(smem + SM_EW);
    float*         log_s = (float*)(smem + SM_LOG);
    float*         bl_s  = (float*)(smem + SM_BL);
    unsigned char* tok_s = (unsigned char*)(smem + SM_TOK);

    const int tid  = threadIdx.x;
    const int lane = tid & 31;
    const int wid  = tid >> 5;     // 0..15
    const int gid  = lane >> 2;    // 0..7
    const int t4   = lane & 3;     // 0..3
    const int b0   = blockIdx.x * NBLK;
    const bool even = ((t4 & 1) == 0);

    // ---- stage W_hh -> bf16 permuted [g'][k] ----
    for (int idx = tid; idx < Gc * Hc; idx += NTHR) {
        int g = idx >> 7, k = idx & 127;
        int gp = (g & 127) * 4 + (g >> 7);
        whh_s[gp * PITCH + k] = __float2bfloat16(W_hh[idx]);
    }
    // ---- stage W_lin -> bf16 [32 padded][k] ----
    for (int idx = tid; idx < 32 * Hc; idx += NTHR) {
        int v = idx >> 7, k = idx & 127;
        wl_s[v * PITCH + k] = (v < Vc) ? __float2bfloat16(W_lin[v * Hc + k])
                                       : __float2bfloat16(0.f);
    }
    // ---- stage h0 -> bf16 ----
    for (int idx = tid; idx < NBLK * Hc; idx += NTHR) {
        int b = idx >> 7, u = idx & 127;
        h_s[b * PITCH + u] = __float2bfloat16(h0[(b0 + b) * Hc + u]);
    }
    // ---- EW table, biases, tokens ----
    for (int idx = tid; idx < Vc * Gc; idx += NTHR) ew_s[idx] = d_EW[idx];
    if (tid < 32) bl_s[tid] = (tid < Vc) ? b_lin[tid] : 0.f;
    for (int idx = tid; idx < NBLK * Tc; idx += NTHR)
        tok_s[idx] = (unsigned char)inpt[b0 * Tc + idx];

    // ---- c state: 8 cells per lane (mt x nt); even lanes rows gid, odd rows gid+8 ----
    float cr[8];
#pragma unroll
    for (int mt = 0; mt < 2; mt++)
#pragma unroll
        for (int nt = 0; nt < 4; nt++) {
            int row = 16 * mt + gid + (even ? 0 : 8);
            int u = 8 * wid + 2 * nt + (t4 >> 1);
            cr[mt * 4 + nt] = c0[(b0 + row) * Hc + u];
        }

    // ---- ldmatrix base addresses ----
    const int m = lane >> 3;   // 0..3
    const uint32_t aA0 = s2u(h_s) +
        ((((m & 1) * 8 + (lane & 7)) * PITCH + (m >> 1) * 8) << 1);
    const uint32_t aA1 = aA0 + 16 * PITCH * 2;
    const uint32_t aB0 = s2u(whh_s) +
        (((32 * wid + (m >> 1) * 8 + (lane & 7)) * PITCH + (m & 1) * 8) << 1);
    const uint32_t aB1 = aB0 + 16 * PITCH * 2;
    const uint32_t aLB = s2u(wl_s) +
        (((16 * (wid >> 1) + (m >> 1) * 8 + (lane & 7)) * PITCH + (m & 1) * 8) << 1);

    // cell-update h store offset (elements): row*PITCH + u (mt=0)
    const int hst0 = (gid + (even ? 0 : 8)) * PITCH + 8 * wid + (t4 >> 1);

    float my_loss = 0.f;

    // CE over log_s rows; y = tok[:,ty], m = mask[:,tm]
    auto ce_pass = [&](int ty, int tm) {
#pragma unroll
        for (int bi = 0; bi < 2; bi++) {
            int row = 2 * wid + bi;
            float lg = (lane < Vc) ? (log_s[row * 36 + lane] + bl_s[lane]) : -1e30f;
            float mx = lg;
#pragma unroll
            for (int o = 16; o; o >>= 1)
                mx = fmaxf(mx, __shfl_xor_sync(0xffffffffu, mx, o));
            float ex = (lane < Vc) ? __expf(lg - mx) : 0.f;
            float sm = ex;
#pragma unroll
            for (int o = 16; o; o >>= 1)
                sm += __shfl_xor_sync(0xffffffffu, sm, o);
            int y = (int)tok_s[row * Tc + ty];
            float ly = __shfl_sync(0xffffffffu, lg, y);
            if (lane == 0)
                my_loss += (mx + __logf(sm) - ly) * mask[(b0 + row) * Tc + tm];
        }
    };

#pragma unroll 1
    for (int t = 0; t < Tc - 1; t++) {
        __syncthreads();   // staging / prev h2 stores visible; log_s free

        // accumulator init from EW'[token]
        int tka0 = tok_s[gid * Tc + t];
        int tkb0 = tok_s[(gid + 8) * Tc + t];
        int tka1 = tok_s[(gid + 16) * Tc + t];
        int tkb1 = tok_s[(gid + 24) * Tc + t];
        float a[2][4][4];
#pragma unroll
        for (int nt = 0; nt < 4; nt++) {
            int col = 32 * wid + 8 * nt + 2 * t4;
            float2 e;
            e = *(const float2*)&ew_s[tka0 * Gc + col]; a[0][nt][0] = e.x; a[0][nt][1] = e.y;
            e = *(const float2*)&ew_s[tkb0 * Gc + col]; a[0][nt][2] = e.x; a[0][nt][3] = e.y;
            e = *(const float2*)&ew_s[tka1 * Gc + col]; a[1][nt][0] = e.x; a[1][nt][1] = e.y;
            e = *(const float2*)&ew_s[tkb1 * Gc + col]; a[1][nt][2] = e.x; a[1][nt][3] = e.y;
        }
        float lacc[2][4] = {{0.f,0.f,0.f,0.f},{0.f,0.f,0.f,0.f}};

#pragma unroll
        for (int ks = 0; ks < 8; ks++) {
            uint32_t A0[4], A1[4], B0[4], B1[4];
            LDSM4(A0, aA0 + ks * 32);
            LDSM4(A1, aA1 + ks * 32);
            LDSM4(B0, aB0 + ks * 32);
            LDSM4(B1, aB1 + ks * 32);
            MMAB(a[0][0], A0, B0[0], B0[1]);
            MMAB(a[0][1], A0, B0[2], B0[3]);
            MMAB(a[0][2], A0, B1[0], B1[1]);
            MMAB(a[0][3], A0, B1[2], B1[3]);
            MMAB(a[1][0], A1, B0[0], B0[1]);
            MMAB(a[1][1], A1, B0[2], B0[3]);
            MMAB(a[1][2], A1, B1[0], B1[1]);
            MMAB(a[1][3], A1, B1[2], B1[3]);
            if (wid < 4 && t > 0) {   // logits of h_t (lagged CE)
                uint32_t LB[4];
                LDSM4(LB, aLB + ks * 32);
                const uint32_t* AL = (wid & 1) ? A1 : A0;
                MMAB(lacc[0], AL, LB[0], LB[1]);
                MMAB(lacc[1], AL, LB[2], LB[3]);
            }
        }
        if (wid < 4 && t > 0) {
            int mtl = wid & 1, np = wid >> 1;
#pragma unroll
            for (int q = 0; q < 2; q++) {
                int cbase = 8 * (2 * np + q) + 2 * t4;
                log_s[(16 * mtl + gid) * 36 + cbase]     = lacc[q][0];
                log_s[(16 * mtl + gid) * 36 + cbase + 1] = lacc[q][1];
                log_s[(16 * mtl + gid + 8) * 36 + cbase]     = lacc[q][2];
                log_s[(16 * mtl + gid + 8) * 36 + cbase + 1] = lacc[q][3];
            }
        }
        __syncthreads();   // all h_s reads done; log_s complete

        // ---- LSTM cell in registers; pairwise gate exchange ----
#pragma unroll
        for (int mt = 0; mt < 2; mt++)
#pragma unroll
            for (int nt = 0; nt < 4; nt++) {
                float d0 = a[mt][nt][0], d1 = a[mt][nt][1];
                float d2 = a[mt][nt][2], d3 = a[mt][nt][3];
                float sa = even ? d2 : d0;
                float sb = even ? d3 : d1;
                float ra = __shfl_xor_sync(0xffffffffu, sa, 1);
                float rb = __shfl_xor_sync(0xffffffffu, sb, 1);
                float iv = even ? d0 : ra;
                float fv = even ? d1 : rb;
                float gv = even ? ra : d2;
                float ov = even ? rb : d3;
                float c2 = fmaf(sigapx(fv), cr[mt * 4 + nt],
                                sigapx(iv) * tanhapx(gv));
                cr[mt * 4 + nt] = c2;
                h_s[hst0 + mt * 16 * PITCH + 2 * nt] =
                    __float2bfloat16(sigapx(ov) * tanhapx(c2));
            }

        if (t > 0) ce_pass(t, t - 1);
    }

    // ---- tail: score h_127 ----
    __syncthreads();
    if (wid < 4) {
        float lacc[2][4] = {{0.f,0.f,0.f,0.f},{0.f,0.f,0.f,0.f}};
        uint32_t aAx = (wid & 1) ? aA1 : aA0;
#pragma unroll
        for (int ks = 0; ks < 8; ks++) {
            uint32_t AL[4], LB[4];
            LDSM4(AL, aAx + ks * 32);
            LDSM4(LB, aLB + ks * 32);
            MMAB(lacc[0], AL, LB[0], LB[1]);
            MMAB(lacc[1], AL, LB[2], LB[3]);
        }
        int mtl = wid & 1, np = wid >> 1;
#pragma unroll
        for (int q = 0; q < 2; q++) {
            int cbase = 8 * (2 * np + q) + 2 * t4;
            log_s[(16 * mtl + gid) * 36 + cbase]     = lacc[q][0];
            log_s[(16 * mtl + gid) * 36 + cbase + 1] = lacc[q][1];
            log_s[(16 * mtl + gid + 8) * 36 + cbase]     = lacc[q][2];
            log_s[(16 * mtl + gid + 8) * 36 + cbase + 1] = lacc[q][3];
        }
    }
    __syncthreads();
    ce_pass(Tc - 1, Tc - 2);

    // ---- block loss reduction ----
#pragma unroll
    for (int o = 16; o; o >>= 1)
        my_loss += __shfl_xor_sync(0xffffffffu, my_loss, o);
    __shared__ float wsum[16];
    if (lane == 0) wsum[wid] = my_loss;
    __syncthreads();
    if (wid == 0) {
        float v = (lane < 16) ? wsum[lane] : 0.f;
#pragma unroll
        for (int o = 8; o; o >>= 1)
            v += __shfl_xor_sync(0xffffffffu, v, o);
        if (lane == 0) atomicAdd(&d_loss_sum, (double)v);
    }
}

__global__ void finalize_kernel(float* out) {
    out[0] = (float)(d_loss_sum / d_mask_sum);
}

extern "C" void kernel_launch(void* const* d_in, const int* in_sizes, int n_in,
                              void* d_out, int out_size) {
    const int*   inpt  = (const int*)d_in[0];
    const float* h0    = (const float*)d_in[1];
    const float* c0    = (const float*)d_in[2];
    const float* mask  = (const float*)d_in[3];
    // d_in[4] = beta (unused)
    const float* emb   = (const float*)d_in[5];
    const float* W_ih  = (const float*)d_in[6];
    const float* b_ih  = (const float*)d_in[7];
    const float* W_hh  = (const float*)d_in[8];
    const float* b_hh  = (const float*)d_in[9];
    const float* W_lin = (const float*)d_in[10];
    const float* b_lin = (const float*)d_in[11];
    float* out = (float*)d_out;

    cudaFuncSetAttribute(lstm_kernel,
                         cudaFuncAttributeMaxDynamicSharedMemorySize, SM_TOTAL);

    zero_kernel<<<1, 1>>>();
    mask_sum_kernel<<<256, 256>>>(mask, Bc * Tc);
    ew_kernel<<<Vc, Gc>>>(emb, W_ih, b_ih, b_hh);
    lstm_kernel<<<Bc / NBLK, NTHR, SM_TOTAL>>>(inpt, h0, c0, mask,
                                               W_hh, W_lin, b_lin);
    finalize_kernel<<<1, 1>>>(out);
}

// round 4
// speedup vs baseline: 7.5295x; 1.0176x over previous
#include <cuda_runtime.h>
#include <cuda_fp16.h>
#include <math.h>
#include <stdint.h>

// Problem dims
#define Bc 4096
#define Tc 128
#define Vc 30
#define Ec 256
#define Hc 128
#define Gc 512      // 4*H
#define NBLK 32     // batch rows per CTA
#define NTHR 512    // 16 warps
#define PITCH 136   // f16 elements per row -> conflict-free ldmatrix
#define HBE  (NBLK * PITCH)        // h buffer stride in elements
#define EWST 544                   // halves per vocab row (512 + pad)
#define LOGST 1152                 // floats per logits buffer (32*36)

// Scratch
__device__ __half d_EW2[Vc * EWST];  // x-side gate table, packed per (wid,t4)
__device__ double d_loss_sum;
__device__ double d_mask_sum;

__global__ void zero_kernel() { d_loss_sum = 0.0; d_mask_sum = 0.0; }

// EW'[v][gp], gp = 4u+j (permuted gate index); packed layout:
// d_EW2[v*544 + wid*32 + t4*8 + nt*2 + j],  gp = 32*wid + 8*nt + 2*t4 + j
__global__ void ew_kernel(const float* __restrict__ emb,
                          const float* __restrict__ W_ih,
                          const float* __restrict__ b_ih,
                          const float* __restrict__ b_hh) {
    __shared__ float ev[Ec];
    int v = blockIdx.x;
    int gp = threadIdx.x;
    int g = (gp & 3) * Hc + (gp >> 2);
    for (int e = threadIdx.x; e < Ec; e += blockDim.x) ev[e] = emb[v * Ec + e];
    __syncthreads();
    float s = b_ih[g] + b_hh[g];
    const float* w = W_ih + g * Ec;
#pragma unroll 8
    for (int e = 0; e < Ec; e++) s += w[e] * ev[e];
    int widx = gp >> 5, rem = gp & 31;
    int nt = rem >> 3, tt = (rem >> 1) & 3, j = rem & 1;
    d_EW2[v * EWST + widx * 32 + tt * 8 + nt * 2 + j] = __float2half(s);
}

__global__ void mask_sum_kernel(const float* __restrict__ mask, int n) {
    double local = 0.0;
    for (int i = blockIdx.x * blockDim.x + threadIdx.x; i < n;
         i += gridDim.x * blockDim.x)
        local += (double)mask[i];
#pragma unroll
    for (int o = 16; o; o >>= 1) local += __shfl_down_sync(0xffffffffu, local, o);
    __shared__ double ws[32];
    int lane = threadIdx.x & 31, w = threadIdx.x >> 5;
    if (lane == 0) ws[w] = local;
    __syncthreads();
    if (w == 0) {
        local = (lane < (int)(blockDim.x >> 5)) ? ws[lane] : 0.0;
#pragma unroll
        for (int o = 16; o; o >>= 1) local += __shfl_down_sync(0xffffffffu, local, o);
        if (lane == 0) atomicAdd(&d_mask_sum, local);
    }
}

__device__ __forceinline__ uint32_t s2u(const void* p) {
    return (uint32_t)__cvta_generic_to_shared(p);
}
__device__ __forceinline__ __half2 tanh2(__half2 x) {
    uint32_t xi = *reinterpret_cast<uint32_t*>(&x), yi;
    asm("tanh.approx.f16x2 %0, %1;" : "=r"(yi) : "r"(xi));
    return *reinterpret_cast<__half2*>(&yi);
}
__device__ __forceinline__ __half2 sig2(__half2 x) {
    const __half2 hh = __float2half2_rn(0.5f);
    return __hfma2(tanh2(__hmul2(x, hh)), hh, hh);
}

#define LDSM4(R, ADDR) \
    asm volatile("ldmatrix.sync.aligned.m8n8.x4.shared.b16 {%0,%1,%2,%3},[%4];" \
        : "=r"(R[0]),"=r"(R[1]),"=r"(R[2]),"=r"(R[3]) : "r"(ADDR))

#define MMAH(D, A, b0, b1) \
    asm volatile("mma.sync.aligned.m16n8k16.row.col.f32.f16.f16.f32 " \
        "{%0,%1,%2,%3},{%4,%5,%6,%7},{%8,%9},{%0,%1,%2,%3};" \
        : "+f"(D[0]),"+f"(D[1]),"+f"(D[2]),"+f"(D[3]) \
        : "r"(A[0]),"r"(A[1]),"r"(A[2]),"r"(A[3]),"r"(b0),"r"(b1))

// SMEM layout (bytes)
#define SM_WHH   0                                   // f16 [512][PITCH]  139264
#define SM_H     (SM_WHH + Gc * PITCH * 2)           // f16 2x[32][PITCH]  17408
#define SM_WL    (SM_H + 2 * NBLK * PITCH * 2)       // f16 [32][PITCH]     8704
#define SM_EW    (SM_WL + 32 * PITCH * 2)            // f16 [30][544]      32640
#define SM_LOG   (SM_EW + Vc * EWST * 2)             // f32 2x[32][36]      9216
#define SM_BL    (SM_LOG + 2 * LOGST * 4)            // f32 [32]             128
#define SM_TOK   (SM_BL + 32 * 4)                    // u8  [32][128]       4096
#define SM_TOTAL (SM_TOK + NBLK * Tc)                //                   211456

__global__ void __launch_bounds__(NTHR, 1)
lstm_kernel(const int* __restrict__ inpt,
            const float* __restrict__ h0,
            const float* __restrict__ c0,
            const float* __restrict__ mask,
            const float* __restrict__ W_hh,
            const float* __restrict__ W_lin,
            const float* __restrict__ b_lin) {
    extern __shared__ char smem[];
    __half*        whh_s = (__half*)(smem + SM_WHH);
    __half*        h_s   = (__half*)(smem + SM_H);     // 2 buffers
    __half*        wl_s  = (__half*)(smem + SM_WL);
    __half*        ew_s  = (__half*)(smem + SM_EW);
    float*         log_s = (float*)(smem + SM_LOG);    // 2 buffers
    float*         bl_s  = (float*)(smem + SM_BL);
    unsigned char* tok_s = (unsigned char*)(smem + SM_TOK);

    const int tid  = threadIdx.x;
    const int lane = tid & 31;
    const int wid  = tid >> 5;     // 0..15
    const int gid  = lane >> 2;    // 0..7
    const int t4   = lane & 3;     // 0..3
    const int b0   = blockIdx.x * NBLK;
    const bool even = ((t4 & 1) == 0);

    // ---- stage W_hh -> f16 permuted [g'][k] ----
    for (int idx = tid; idx < Gc * Hc; idx += NTHR) {
        int g = idx >> 7, k = idx & 127;
        int gp = (g & 127) * 4 + (g >> 7);
        whh_s[gp * PITCH + k] = __float2half(W_hh[idx]);
    }
    // ---- stage W_lin -> f16 [32 padded][k] ----
    for (int idx = tid; idx < 32 * Hc; idx += NTHR) {
        int v = idx >> 7, k = idx & 127;
        wl_s[v * PITCH + k] = (v < Vc) ? __float2half(W_lin[v * Hc + k])
                                       : __float2half(0.f);
    }
    // ---- stage h0 -> f16 buffer 0 ----
    for (int idx = tid; idx < NBLK * Hc; idx += NTHR) {
        int b = idx >> 7, u = idx & 127;
        h_s[b * PITCH + u] = __float2half(h0[(b0 + b) * Hc + u]);
    }
    // ---- EW packed table, biases, tokens ----
    {
        uint32_t* d32 = (uint32_t*)ew_s;
        const uint32_t* s32 = (const uint32_t*)d_EW2;
        for (int i = tid; i < Vc * EWST / 2; i += NTHR) d32[i] = s32[i];
    }
    if (tid < 32) bl_s[tid] = (tid < Vc) ? b_lin[tid] : 0.f;
    for (int idx = tid; idx < NBLK * Tc; idx += NTHR)
        tok_s[idx] = (unsigned char)inpt[b0 * Tc + idx];

    // ---- c state ----
    float cr[8];
#pragma unroll
    for (int mt = 0; mt < 2; mt++)
#pragma unroll
        for (int nt = 0; nt < 4; nt++) {
            int row = 16 * mt + gid + (even ? 0 : 8);
            int u = 8 * wid + 2 * nt + (t4 >> 1);
            cr[mt * 4 + nt] = c0[(b0 + row) * Hc + u];
        }

    // ---- ldmatrix patterns ----
    const int m = lane >> 3;   // 0..3
    const uint32_t hs_base = s2u(h_s);
    const uint32_t aA_pat = ((((m & 1) * 8 + (lane & 7)) * PITCH + (m >> 1) * 8) << 1);
    const uint32_t aB0 = s2u(whh_s) +
        (((32 * wid + (m >> 1) * 8 + (lane & 7)) * PITCH + (m & 1) * 8) << 1);
    const uint32_t aB1 = aB0 + 16 * PITCH * 2;
    const uint32_t aLB = s2u(wl_s) +
        (((16 * (wid >> 1) + (m >> 1) * 8 + (lane & 7)) * PITCH + (m & 1) * 8) << 1);
    const int hst0 = (gid + (even ? 0 : 8)) * PITCH + 8 * wid + (t4 >> 1);
    const int ew_off = wid * 32 + t4 * 8;

    __syncthreads();   // staging visible

    // ---- W_hh fragments -> registers (once) ----
    uint32_t breg[8][8];
#pragma unroll
    for (int ks = 0; ks < 8; ks++) {
        LDSM4((&breg[ks][0]), aB0 + ks * 32);
        LDSM4((&breg[ks][4]), aB1 + ks * 32);
    }

    float my_loss = 0.f;

    // CE over a logits buffer; y = tok[:,ty], m = mask[:,tm]
    auto ce_pass = [&](const float* lbuf, int ty, int tm) {
#pragma unroll
        for (int bi = 0; bi < 2; bi++) {
            int row = 2 * wid + bi;
            float lg = (lane < Vc) ? (lbuf[row * 36 + lane] + bl_s[lane]) : -1e30f;
            float mx = lg;
#pragma unroll
            for (int o = 16; o; o >>= 1)
                mx = fmaxf(mx, __shfl_xor_sync(0xffffffffu, mx, o));
            float ex = (lane < Vc) ? __expf(lg - mx) : 0.f;
            float sm = ex;
#pragma unroll
            for (int o = 16; o; o >>= 1)
                sm += __shfl_xor_sync(0xffffffffu, sm, o);
            int y = (int)tok_s[row * Tc + ty];
            float ly = __shfl_sync(0xffffffffu, lg, y);
            if (lane == 0)
                my_loss += (mx + __logf(sm) - ly) * mask[(b0 + row) * Tc + tm];
        }
    };

    // logits of h in buffer `cb` -> log_s buffer `cb` (warps 0..3)
    auto logits_pass = [&](int cb) {
        float lacc[8] = {0.f,0.f,0.f,0.f,0.f,0.f,0.f,0.f};
        uint32_t aAx = hs_base + cb * (HBE * 2) + aA_pat + (wid & 1) * (16 * PITCH * 2);
        float* lout = log_s + cb * LOGST;
#pragma unroll
        for (int ks = 0; ks < 8; ks++) {
            uint32_t AL[4], LB[4];
            LDSM4(AL, aAx + ks * 32);
            LDSM4(LB, aLB + ks * 32);
            MMAH((&lacc[0]), AL, LB[0], LB[1]);
            MMAH((&lacc[4]), AL, LB[2], LB[3]);
        }
        int mtl = wid & 1, np = wid >> 1;
#pragma unroll
        for (int q = 0; q < 2; q++) {
            int cbase = 8 * (2 * np + q) + 2 * t4;
            lout[(16 * mtl + gid) * 36 + cbase]         = lacc[4 * q];
            lout[(16 * mtl + gid) * 36 + cbase + 1]     = lacc[4 * q + 1];
            lout[(16 * mtl + gid + 8) * 36 + cbase]     = lacc[4 * q + 2];
            lout[(16 * mtl + gid + 8) * 36 + cbase + 1] = lacc[4 * q + 3];
        }
    };

#pragma unroll 1
    for (int t = 0; t < Tc - 1; t++) {
        const int cur = t & 1, nxt = cur ^ 1;
        __syncthreads();   // prev h / log_s writes visible

        // logits(h_t) for t>=1 into log_s[cur]
        if (wid < 4 && t > 0) logits_pass(cur);
        // consume logits(h_{t-1}) from log_s[nxt]
        if (t > 1) ce_pass(log_s + nxt * LOGST, t - 1, t - 2);

        // ---- accumulator init from packed EW (f16, LDS.128) ----
        int tka0 = tok_s[gid * Tc + t];
        int tkb0 = tok_s[(gid + 8) * Tc + t];
        int tka1 = tok_s[(gid + 16) * Tc + t];
        int tkb1 = tok_s[(gid + 24) * Tc + t];
        uint4 qa0 = *(const uint4*)&ew_s[tka0 * EWST + ew_off];
        uint4 qb0 = *(const uint4*)&ew_s[tkb0 * EWST + ew_off];
        uint4 qa1 = *(const uint4*)&ew_s[tka1 * EWST + ew_off];
        uint4 qb1 = *(const uint4*)&ew_s[tkb1 * EWST + ew_off];
        float a[2][4][4];
        {
            float2 f;
            f = __half22float2(*(__half2*)&qa0.x); a[0][0][0]=f.x; a[0][0][1]=f.y;
            f = __half22float2(*(__half2*)&qa0.y); a[0][1][0]=f.x; a[0][1][1]=f.y;
            f = __half22float2(*(__half2*)&qa0.z); a[0][2][0]=f.x; a[0][2][1]=f.y;
            f = __half22float2(*(__half2*)&qa0.w); a[0][3][0]=f.x; a[0][3][1]=f.y;
            f = __half22float2(*(__half2*)&qb0.x); a[0][0][2]=f.x; a[0][0][3]=f.y;
            f = __half22float2(*(__half2*)&qb0.y); a[0][1][2]=f.x; a[0][1][3]=f.y;
            f = __half22float2(*(__half2*)&qb0.z); a[0][2][2]=f.x; a[0][2][3]=f.y;
            f = __half22float2(*(__half2*)&qb0.w); a[0][3][2]=f.x; a[0][3][3]=f.y;
            f = __half22float2(*(__half2*)&qa1.x); a[1][0][0]=f.x; a[1][0][1]=f.y;
            f = __half22float2(*(__half2*)&qa1.y); a[1][1][0]=f.x; a[1][1][1]=f.y;
            f = __half22float2(*(__half2*)&qa1.z); a[1][2][0]=f.x; a[1][2][1]=f.y;
            f = __half22float2(*(__half2*)&qa1.w); a[1][3][0]=f.x; a[1][3][1]=f.y;
            f = __half22float2(*(__half2*)&qb1.x); a[1][0][2]=f.x; a[1][0][3]=f.y;
            f = __half22float2(*(__half2*)&qb1.y); a[1][1][2]=f.x; a[1][1][3]=f.y;
            f = __half22float2(*(__half2*)&qb1.z); a[1][2][2]=f.x; a[1][2][3]=f.y;
            f = __half22float2(*(__half2*)&qb1.w); a[1][3][2]=f.x; a[1][3][3]=f.y;
        }

        // ---- main gates MMA: A from h[cur], B from registers ----
        const uint32_t aA0c = hs_base + cur * (HBE * 2) + aA_pat;
        const uint32_t aA1c = aA0c + 16 * PITCH * 2;
#pragma unroll
        for (int ks = 0; ks < 8; ks++) {
            uint32_t A0[4], A1[4];
            LDSM4(A0, aA0c + ks * 32);
            LDSM4(A1, aA1c + ks * 32);
            MMAH(a[0][0], A0, breg[ks][0], breg[ks][1]);
            MMAH(a[0][1], A0, breg[ks][2], breg[ks][3]);
            MMAH(a[0][2], A0, breg[ks][4], breg[ks][5]);
            MMAH(a[0][3], A0, breg[ks][6], breg[ks][7]);
            MMAH(a[1][0], A1, breg[ks][0], breg[ks][1]);
            MMAH(a[1][1], A1, breg[ks][2], breg[ks][3]);
            MMAH(a[1][2], A1, breg[ks][4], breg[ks][5]);
            MMAH(a[1][3], A1, breg[ks][6], breg[ks][7]);
        }

        // ---- LSTM cell: pairwise gate exchange + f16x2 activations ----
        __half* hnxt = h_s + nxt * HBE;
#pragma unroll
        for (int mt = 0; mt < 2; mt++)
#pragma unroll
            for (int q = 0; q < 2; q++) {
                float iv[2], fv[2], gv[2], ov[2];
#pragma unroll
                for (int s = 0; s < 2; s++) {
                    int nt = 2 * q + s;
                    float d0 = a[mt][nt][0], d1 = a[mt][nt][1];
                    float d2 = a[mt][nt][2], d3 = a[mt][nt][3];
                    float sa = even ? d2 : d0;
                    float sb = even ? d3 : d1;
                    float ra = __shfl_xor_sync(0xffffffffu, sa, 1);
                    float rb = __shfl_xor_sync(0xffffffffu, sb, 1);
                    iv[s] = even ? d0 : ra;
                    fv[s] = even ? d1 : rb;
                    gv[s] = even ? ra : d2;
                    ov[s] = even ? rb : d3;
                }
                __half2 i2 = __floats2half2_rn(iv[0], iv[1]);
                __half2 f2 = __floats2half2_rn(fv[0], fv[1]);
                __half2 g2 = __floats2half2_rn(gv[0], gv[1]);
                __half2 o2 = __floats2half2_rn(ov[0], ov[1]);
                __half2 si = sig2(i2), sf = sig2(f2), so = sig2(o2);
                __half2 tg = tanh2(g2);
                __half2 it = __hmul2(si, tg);
                int ci = mt * 4 + 2 * q;
                float c2a = fmaf(__low2float(sf),  cr[ci],     __low2float(it));
                float c2b = fmaf(__high2float(sf), cr[ci + 1], __high2float(it));
                cr[ci] = c2a; cr[ci + 1] = c2b;
                __half2 hh = __hmul2(so, tanh2(__floats2half2_rn(c2a, c2b)));
                hnxt[hst0 + mt * 16 * PITCH + 4 * q]     = __low2half(hh);
                hnxt[hst0 + mt * 16 * PITCH + 4 * q + 2] = __high2half(hh);
            }
    }

    // ---- tail: consume h_126, score + consume h_127 ----
    __syncthreads();
    ce_pass(log_s + 0 * LOGST, Tc - 2, Tc - 3);   // logits(h_126) in buffer 0
    if (wid < 4) logits_pass(1);                  // h_127 lives in buffer 1
    __syncthreads();
    ce_pass(log_s + 1 * LOGST, Tc - 1, Tc - 2);

    // ---- block loss reduction ----
#pragma unroll
    for (int o = 16; o; o >>= 1)
        my_loss += __shfl_xor_sync(0xffffffffu, my_loss, o);
    __shared__ float wsum[16];
    if (lane == 0) wsum[wid] = my_loss;
    __syncthreads();
    if (wid == 0) {
        float v = (lane < 16) ? wsum[lane] : 0.f;
#pragma unroll
        for (int o = 8; o; o >>= 1)
            v += __shfl_xor_sync(0xffffffffu, v, o);
        if (lane == 0) atomicAdd(&d_loss_sum, (double)v);
    }
}

__global__ void finalize_kernel(float* out) {
    out[0] = (float)(d_loss_sum / d_mask_sum);
}

extern "C" void kernel_launch(void* const* d_in, const int* in_sizes, int n_in,
                              void* d_out, int out_size) {
    const int*   inpt  = (const int*)d_in[0];
    const float* h0    = (const float*)d_in[1];
    const float* c0    = (const float*)d_in[2];
    const float* mask  = (const float*)d_in[3];
    // d_in[4] = beta (unused)
    const float* emb   = (const float*)d_in[5];
    const float* W_ih  = (const float*)d_in[6];
    const float* b_ih  = (const float*)d_in[7];
    const float* W_hh  = (const float*)d_in[8];
    const float* b_hh  = (const float*)d_in[9];
    const float* W_lin = (const float*)d_in[10];
    const float* b_lin = (const float*)d_in[11];
    float* out = (float*)d_out;

    cudaFuncSetAttribute(lstm_kernel,
                         cudaFuncAttributeMaxDynamicSharedMemorySize, SM_TOTAL);

    zero_kernel<<<1, 1>>>();
    mask_sum_kernel<<<256, 256>>>(mask, Bc * Tc);
    ew_kernel<<<Vc, Gc>>>(emb, W_ih, b_ih, b_hh);
    lstm_kernel<<<Bc / NBLK, NTHR, SM_TOTAL>>>(inpt, h0, c0, mask,
                                               W_hh, W_lin, b_lin);
    finalize_kernel<<<1, 1>>>(out);
}

// round 5
// speedup vs baseline: 8.8569x; 1.1763x over previous
#include <cuda_runtime.h>
#include <cuda_fp16.h>
#include <math.h>
#include <stdint.h>

// Problem dims
#define Bc 4096
#define Tc 128
#define Vc 30
#define Ec 256
#define Hc 128
#define Gc 512      // 4*H
#define NBLK 32     // batch rows per CTA
#define NTHR 512    // 16 warps
#define PITCH 136   // f16 elements per row -> conflict-free ldmatrix
#define HBE  (NBLK * PITCH)        // h buffer stride (elements)
#define EWST 544                   // halves per vocab row (512 + pad)
#define LOGSTP 1152                // floats per logits partial buffer (32*36)

// Scratch
__device__ __half d_EW2[Vc * EWST];  // x-side gate table (new permutation), packed
__device__ double d_loss_sum;
__device__ double d_mask_sum;

__global__ void zero_kernel() { d_loss_sum = 0.0; d_mask_sum = 0.0; }

// Permutation: gp bits [8:5]=wid, [4]=q, [3]=s, [2:1]=t4, [0]=j
//   gate = 2s + j (i,f,g,o) ; u = 8*wid + 4*q + t4 ; orig g = gate*128 + u
// Packed EW layout: d_EW2[v*544 + wid*32 + t4*8 + nt*2 + j], nt = 2q+s
__global__ void ew_kernel(const float* __restrict__ emb,
                          const float* __restrict__ W_ih,
                          const float* __restrict__ b_ih,
                          const float* __restrict__ b_hh) {
    __shared__ float ev[Ec];
    int v = blockIdx.x;
    int gp = threadIdx.x;
    int widx = gp >> 5, q = (gp >> 4) & 1, s = (gp >> 3) & 1;
    int t4p = (gp >> 1) & 3, j = gp & 1;
    int gate = 2 * s + j;
    int u = 8 * widx + 4 * q + t4p;
    int g = gate * Hc + u;
    for (int e = threadIdx.x; e < Ec; e += blockDim.x) ev[e] = emb[v * Ec + e];
    __syncthreads();
    float acc = b_ih[g] + b_hh[g];
    const float* w = W_ih + g * Ec;
#pragma unroll 8
    for (int e = 0; e < Ec; e++) acc += w[e] * ev[e];
    int nt = 2 * q + s;
    d_EW2[v * EWST + widx * 32 + t4p * 8 + nt * 2 + j] = __float2half(acc);
}

__global__ void mask_sum_kernel(const float* __restrict__ mask, int n) {
    double local = 0.0;
    for (int i = blockIdx.x * blockDim.x + threadIdx.x; i < n;
         i += gridDim.x * blockDim.x)
        local += (double)mask[i];
#pragma unroll
    for (int o = 16; o; o >>= 1) local += __shfl_down_sync(0xffffffffu, local, o);
    __shared__ double ws[32];
    int lane = threadIdx.x & 31, w = threadIdx.x >> 5;
    if (lane == 0) ws[w] = local;
    __syncthreads();
    if (w == 0) {
        local = (lane < (int)(blockDim.x >> 5)) ? ws[lane] : 0.0;
#pragma unroll
        for (int o = 16; o; o >>= 1) local += __shfl_down_sync(0xffffffffu, local, o);
        if (lane == 0) atomicAdd(&d_mask_sum, local);
    }
}

__device__ __forceinline__ uint32_t s2u(const void* p) {
    return (uint32_t)__cvta_generic_to_shared(p);
}
__device__ __forceinline__ __half2 tanh2(__half2 x) {
    uint32_t xi = *reinterpret_cast<uint32_t*>(&x), yi;
    asm("tanh.approx.f16x2 %0, %1;" : "=r"(yi) : "r"(xi));
    return *reinterpret_cast<__half2*>(&yi);
}
__device__ __forceinline__ __half2 sig2(__half2 x) {
    const __half2 hh = __float2half2_rn(0.5f);
    return __hfma2(tanh2(__hmul2(x, hh)), hh, hh);
}

#define LDSM4(R, ADDR) \
    asm volatile("ldmatrix.sync.aligned.m8n8.x4.shared.b16 {%0,%1,%2,%3},[%4];" \
        : "=r"(R[0]),"=r"(R[1]),"=r"(R[2]),"=r"(R[3]) : "r"(ADDR))

#define MMAH(D, A, b0, b1) \
    asm volatile("mma.sync.aligned.m16n8k16.row.col.f32.f16.f16.f32 " \
        "{%0,%1,%2,%3},{%4,%5,%6,%7},{%8,%9},{%0,%1,%2,%3};" \
        : "+f"(D[0]),"+f"(D[1]),"+f"(D[2]),"+f"(D[3]) \
        : "r"(A[0]),"r"(A[1]),"r"(A[2]),"r"(A[3]),"r"(b0),"r"(b1))

// SMEM layout (bytes)
#define SM_WHH   0                                   // f16 [512][PITCH]  139264
#define SM_H     (SM_WHH + Gc * PITCH * 2)           // f16 2x[32][PITCH]  17408
#define SM_WL    (SM_H + 2 * NBLK * PITCH * 2)       // f16 [32][PITCH]     8704
#define SM_EW    (SM_WL + 32 * PITCH * 2)            // f16 [30][544]      32640
#define SM_LOG   (SM_EW + Vc * EWST * 2)             // f32 4x[32][36]     18432
#define SM_BL    (SM_LOG + 4 * LOGSTP * 4)           // f32 [32]             128
#define SM_TOK   (SM_BL + 32 * 4)                    // u8  [32][128]       4096
#define SM_TOTAL (SM_TOK + NBLK * Tc)                //                   220672

__global__ void __launch_bounds__(NTHR, 1)
lstm_kernel(const int* __restrict__ inpt,
            const float* __restrict__ h0,
            const float* __restrict__ c0,
            const float* __restrict__ mask,
            const float* __restrict__ W_hh,
            const float* __restrict__ W_lin,
            const float* __restrict__ b_lin) {
    extern __shared__ char smem[];
    __half*        whh_s = (__half*)(smem + SM_WHH);
    __half*        h_s   = (__half*)(smem + SM_H);     // 2 buffers
    __half*        wl_s  = (__half*)(smem + SM_WL);
    __half*        ew_s  = (__half*)(smem + SM_EW);
    float*         log_s = (float*)(smem + SM_LOG);    // 2 time x 2 k-partial
    float*         bl_s  = (float*)(smem + SM_BL);
    unsigned char* tok_s = (unsigned char*)(smem + SM_TOK);

    const int tid  = threadIdx.x;
    const int lane = tid & 31;
    const int wid  = tid >> 5;     // 0..15
    const int gid  = lane >> 2;    // 0..7
    const int t4   = lane & 3;     // 0..3
    const int b0   = blockIdx.x * NBLK;

    // ---- stage W_hh -> f16, new permutation [gp][k] ----
    for (int idx = tid; idx < Gc * Hc; idx += NTHR) {
        int g = idx >> 7, k = idx & 127;
        int u = g & 127, gate = g >> 7;
        int gp = (u >> 3) * 32 + ((u >> 2) & 1) * 16 + (gate >> 1) * 8
               + (u & 3) * 2 + (gate & 1);
        whh_s[gp * PITCH + k] = __float2half(W_hh[idx]);
    }
    // ---- stage W_lin -> f16 [32 padded][k] ----
    for (int idx = tid; idx < 32 * Hc; idx += NTHR) {
        int v = idx >> 7, k = idx & 127;
        wl_s[v * PITCH + k] = (v < Vc) ? __float2half(W_lin[v * Hc + k])
                                       : __float2half(0.f);
    }
    // ---- stage h0 -> f16 buffer 0 ----
    for (int idx = tid; idx < NBLK * Hc; idx += NTHR) {
        int b = idx >> 7, u = idx & 127;
        h_s[b * PITCH + u] = __float2half(h0[(b0 + b) * Hc + u]);
    }
    // ---- EW packed table, biases, tokens ----
    {
        uint32_t* d32 = (uint32_t*)ew_s;
        const uint32_t* s32 = (const uint32_t*)d_EW2;
        for (int i = tid; i < Vc * EWST / 2; i += NTHR) d32[i] = s32[i];
    }
    if (tid < 32) bl_s[tid] = (tid < Vc) ? b_lin[tid] : 0.f;
    for (int idx = tid; idx < NBLK * Tc; idx += NTHR)
        tok_s[idx] = (unsigned char)inpt[b0 * Tc + idx];

    // ---- c state: cr[mt*4 + 2q + rh], row = 16mt+gid+8rh, u = 8wid+4q+t4 ----
    float cr[8];
#pragma unroll
    for (int mt = 0; mt < 2; mt++)
#pragma unroll
        for (int q = 0; q < 2; q++)
#pragma unroll
            for (int rh = 0; rh < 2; rh++)
                cr[mt * 4 + 2 * q + rh] =
                    c0[(b0 + 16 * mt + gid + 8 * rh) * Hc + 8 * wid + 4 * q + t4];

    // ---- ldmatrix patterns ----
    const int m = lane >> 3;   // 0..3
    const uint32_t hs_base = s2u(h_s);
    const uint32_t aA_pat = ((((m & 1) * 8 + (lane & 7)) * PITCH + (m >> 1) * 8) << 1);
    const uint32_t aB0 = s2u(whh_s) +
        (((32 * wid + (m >> 1) * 8 + (lane & 7)) * PITCH + (m & 1) * 8) << 1);
    const uint32_t aB1 = aB0 + 16 * PITCH * 2;
    const int ew_off = wid * 32 + t4 * 8;

    __syncthreads();   // staging visible

    // ---- W_hh fragments -> registers (once) ----
    uint32_t breg[8][8];
#pragma unroll
    for (int ks = 0; ks < 8; ks++) {
        LDSM4((&breg[ks][0]), aB0 + ks * 32);
        LDSM4((&breg[ks][4]), aB1 + ks * 32);
    }

    float my_loss = 0.f;

    // logits of h-buffer hb -> partial buffers pair pb (all 16 warps)
    const int l_kh = wid & 1, l_n8 = (wid >> 1) & 3, l_mt = wid >> 3;
    const uint32_t aBL = s2u(wl_s) +
        (((8 * l_n8 + (lane & 7)) * PITCH + 64 * l_kh + (lane >> 3) * 8) << 1);
    auto logits_pass = [&](int hb, int pb) {
        float lacc[4] = {0.f, 0.f, 0.f, 0.f};
        uint32_t aA = hs_base + hb * (HBE * 2) + aA_pat
                    + l_mt * (16 * PITCH * 2) + l_kh * 128;
        uint32_t B[8];
        LDSM4((&B[0]), aBL);
        LDSM4((&B[4]), aBL + 64);
#pragma unroll
        for (int c = 0; c < 4; c++) {
            uint32_t A[4];
            LDSM4(A, aA + c * 32);
            MMAH(lacc, A, B[2 * c], B[2 * c + 1]);
        }
        float* lout = log_s + (pb * 2 + l_kh) * LOGSTP;
        int r0 = (16 * l_mt + gid) * 36 + 8 * l_n8 + 2 * t4;
        *(float2*)&lout[r0]          = make_float2(lacc[0], lacc[1]);
        *(float2*)&lout[r0 + 8 * 36] = make_float2(lacc[2], lacc[3]);
    };

    // CE over logits pair pb; y = tok[:,ty], m = mask[:,tm]
    auto ce_pass = [&](int pb, int ty, int tm) {
        const float* lb0 = log_s + pb * 2 * LOGSTP;
        const float* lb1 = lb0 + LOGSTP;
#pragma unroll
        for (int bi = 0; bi < 2; bi++) {
            int row = 2 * wid + bi;
            float lg = (lane < Vc)
                ? (lb0[row * 36 + lane] + lb1[row * 36 + lane] + bl_s[lane])
                : -1e30f;
            float mx = lg;
#pragma unroll
            for (int o = 16; o; o >>= 1)
                mx = fmaxf(mx, __shfl_xor_sync(0xffffffffu, mx, o));
            float ex = (lane < Vc) ? __expf(lg - mx) : 0.f;
            float sm = ex;
#pragma unroll
            for (int o = 16; o; o >>= 1)
                sm += __shfl_xor_sync(0xffffffffu, sm, o);
            int y = (int)tok_s[row * Tc + ty];
            float ly = __shfl_sync(0xffffffffu, lg, y);
            if (lane == 0)
                my_loss += (mx + __logf(sm) - ly) * mask[(b0 + row) * Tc + tm];
        }
    };

#pragma unroll 1
    for (int t = 0; t < Tc - 1; t++) {
        const int cur = t & 1, nxt = cur ^ 1;
        __syncthreads();   // prev h / logits partial writes visible

        // ---- accumulator init from packed EW (4x LDS.128) ----
        int tka0 = tok_s[gid * Tc + t];
        int tkb0 = tok_s[(gid + 8) * Tc + t];
        int tka1 = tok_s[(gid + 16) * Tc + t];
        int tkb1 = tok_s[(gid + 24) * Tc + t];
        uint4 qa0 = *(const uint4*)&ew_s[tka0 * EWST + ew_off];
        uint4 qb0 = *(const uint4*)&ew_s[tkb0 * EWST + ew_off];
        uint4 qa1 = *(const uint4*)&ew_s[tka1 * EWST + ew_off];
        uint4 qb1 = *(const uint4*)&ew_s[tkb1 * EWST + ew_off];
        float a[2][4][4];
        {
            const uint32_t* pa0 = &qa0.x;
            const uint32_t* pb0v = &qb0.x;
            const uint32_t* pa1 = &qa1.x;
            const uint32_t* pb1v = &qb1.x;
#pragma unroll
            for (int nt = 0; nt < 4; nt++) {
                float2 f;
                f = __half22float2(*(__half2*)&pa0[nt]);  a[0][nt][0]=f.x; a[0][nt][1]=f.y;
                f = __half22float2(*(__half2*)&pb0v[nt]); a[0][nt][2]=f.x; a[0][nt][3]=f.y;
                f = __half22float2(*(__half2*)&pa1[nt]);  a[1][nt][0]=f.x; a[1][nt][1]=f.y;
                f = __half22float2(*(__half2*)&pb1v[nt]); a[1][nt][2]=f.x; a[1][nt][3]=f.y;
            }
        }

        // ---- main gates MMA: A from h[cur], B from registers ----
        const uint32_t aA0c = hs_base + cur * (HBE * 2) + aA_pat;
        const uint32_t aA1c = aA0c + 16 * PITCH * 2;
#pragma unroll
        for (int ks = 0; ks < 8; ks++) {
            uint32_t A0[4], A1[4];
            LDSM4(A0, aA0c + ks * 32);
            LDSM4(A1, aA1c + ks * 32);
            MMAH(a[0][0], A0, breg[ks][0], breg[ks][1]);
            MMAH(a[0][1], A0, breg[ks][2], breg[ks][3]);
            MMAH(a[0][2], A0, breg[ks][4], breg[ks][5]);
            MMAH(a[0][3], A0, breg[ks][6], breg[ks][7]);
            MMAH(a[1][0], A1, breg[ks][0], breg[ks][1]);
            MMAH(a[1][1], A1, breg[ks][2], breg[ks][3]);
            MMAH(a[1][2], A1, breg[ks][4], breg[ks][5]);
            MMAH(a[1][3], A1, breg[ks][6], breg[ks][7]);
        }

        // ---- independent work while MMAs retire: logits + CE ----
        if (t > 0) logits_pass(cur, cur);
        if (t > 1) ce_pass(nxt, t - 1, t - 2);

        // ---- LSTM cell: fully thread-local gates (no shfl) ----
        __half* hn = h_s + nxt * HBE;
#pragma unroll
        for (int mt = 0; mt < 2; mt++)
#pragma unroll
            for (int q = 0; q < 2; q++) {
                // rows gid (low) and gid+8 (high) of this u = 8wid+4q+t4
                __half2 i2 = __floats2half2_rn(a[mt][2*q][0],   a[mt][2*q][2]);
                __half2 f2 = __floats2half2_rn(a[mt][2*q][1],   a[mt][2*q][3]);
                __half2 g2 = __floats2half2_rn(a[mt][2*q+1][0], a[mt][2*q+1][2]);
                __half2 o2 = __floats2half2_rn(a[mt][2*q+1][1], a[mt][2*q+1][3]);
                __half2 si = sig2(i2), sf = sig2(f2), so = sig2(o2);
                __half2 tg = tanh2(g2);
                __half2 it = __hmul2(si, tg);
                int ci = mt * 4 + 2 * q;
                float c2a = fmaf(__low2float(sf),  cr[ci],     __low2float(it));
                float c2b = fmaf(__high2float(sf), cr[ci + 1], __high2float(it));
                cr[ci] = c2a; cr[ci + 1] = c2b;
                __half2 hh = __hmul2(so, tanh2(__floats2half2_rn(c2a, c2b)));
                int u = 8 * wid + 4 * q + t4;
                hn[(16 * mt + gid) * PITCH + u]     = __low2half(hh);
                hn[(16 * mt + gid + 8) * PITCH + u] = __high2half(hh);
            }
    }

    // ---- tail: consume logits(h_126); score + consume h_127 ----
    __syncthreads();
    ce_pass(0, Tc - 2, Tc - 3);      // logits(h_126) stored at t=126 into pair 0
    logits_pass(1, 1);               // h_127 lives in buffer 1 -> pair 1
    __syncthreads();
    ce_pass(1, Tc - 1, Tc - 2);

    // ---- block loss reduction ----
#pragma unroll
    for (int o = 16; o; o >>= 1)
        my_loss += __shfl_xor_sync(0xffffffffu, my_loss, o);
    __shared__ float wsum[16];
    if (lane == 0) wsum[wid] = my_loss;
    __syncthreads();
    if (wid == 0) {
        float v = (lane < 16) ? wsum[lane] : 0.f;
#pragma unroll
        for (int o = 8; o; o >>= 1)
            v += __shfl_xor_sync(0xffffffffu, v, o);
        if (lane == 0) atomicAdd(&d_loss_sum, (double)v);
    }
}

__global__ void finalize_kernel(float* out) {
    out[0] = (float)(d_loss_sum / d_mask_sum);
}

extern "C" void kernel_launch(void* const* d_in, const int* in_sizes, int n_in,
                              void* d_out, int out_size) {
    const int*   inpt  = (const int*)d_in[0];
    const float* h0    = (const float*)d_in[1];
    const float* c0    = (const float*)d_in[2];
    const float* mask  = (const float*)d_in[3];
    // d_in[4] = beta (unused)
    const float* emb   = (const float*)d_in[5];
    const float* W_ih  = (const float*)d_in[6];
    const float* b_ih  = (const float*)d_in[7];
    const float* W_hh  = (const float*)d_in[8];
    const float* b_hh  = (const float*)d_in[9];
    const float* W_lin = (const float*)d_in[10];
    const float* b_lin = (const float*)d_in[11];
    float* out = (float*)d_out;

    cudaFuncSetAttribute(lstm_kernel,
                         cudaFuncAttributeMaxDynamicSharedMemorySize, SM_TOTAL);

    zero_kernel<<<1, 1>>>();
    mask_sum_kernel<<<256, 256>>>(mask, Bc * Tc);
    ew_kernel<<<Vc, Gc>>>(emb, W_ih, b_ih, b_hh);
    lstm_kernel<<<Bc / NBLK, NTHR, SM_TOTAL>>>(inpt, h0, c0, mask,
                                               W_hh, W_lin, b_lin);
    finalize_kernel<<<1, 1>>>(out);
}

// round 6
// speedup vs baseline: 10.1498x; 1.1460x over previous
#include <cuda_runtime.h>
#include <cuda_fp16.h>
#include <math.h>
#include <stdint.h>

// Problem dims
#define Bc 4096
#define Tc 128
#define Vc 30
#define Ec 256
#define Hc 128
#define Gc 512      // 4*H
#define NBLK 32     // batch rows per CTA (two independent halves of 16)
#define NTHR 512    // 16 warps
#define PITCH 136   // f16 elements per row -> conflict-free ldmatrix
#define HBE  (NBLK * PITCH)        // h buffer stride (elements)
#define EWST 544                   // halves per vocab row (512 + pad)
#define LOGSTP 1152                // floats per logits partial buffer (32*36)

// Scratch
__device__ __half d_EW2[Vc * EWST];
__device__ double d_loss_sum;
__device__ double d_mask_sum;

__global__ void zero_kernel() { d_loss_sum = 0.0; d_mask_sum = 0.0; }

// Storage idx in [0,512): hw=idx>>6, t4=(idx>>4)&3, e=idx&15, nt=e>>1, j=e&1
//   p = nt>>1, gb = nt&1, gate = 2*gb + j, u = 16*hw + 4*p + t4, g = gate*128+u
__global__ void ew_kernel(const float* __restrict__ emb,
                          const float* __restrict__ W_ih,
                          const float* __restrict__ b_ih,
                          const float* __restrict__ b_hh) {
    __shared__ float ev[Ec];
    int v = blockIdx.x;
    int idx = threadIdx.x;
    int hw = idx >> 6, t4p = (idx >> 4) & 3, e = idx & 15;
    int nt = e >> 1, j = e & 1;
    int p = nt >> 1, gb = nt & 1;
    int gate = 2 * gb + j;
    int u = 16 * hw + 4 * p + t4p;
    int g = gate * Hc + u;
    for (int ee = threadIdx.x; ee < Ec; ee += blockDim.x) ev[ee] = emb[v * Ec + ee];
    __syncthreads();
    float acc = b_ih[g] + b_hh[g];
    const float* w = W_ih + g * Ec;
#pragma unroll 8
    for (int ee = 0; ee < Ec; ee++) acc += w[ee] * ev[ee];
    d_EW2[v * EWST + idx] = __float2half(acc);
}

__global__ void mask_sum_kernel(const float* __restrict__ mask, int n) {
    double local = 0.0;
    for (int i = blockIdx.x * blockDim.x + threadIdx.x; i < n;
         i += gridDim.x * blockDim.x)
        local += (double)mask[i];
#pragma unroll
    for (int o = 16; o; o >>= 1) local += __shfl_down_sync(0xffffffffu, local, o);
    __shared__ double ws[32];
    int lane = threadIdx.x & 31, w = threadIdx.x >> 5;
    if (lane == 0) ws[w] = local;
    __syncthreads();
    if (w == 0) {
        local = (lane < (int)(blockDim.x >> 5)) ? ws[lane] : 0.0;
#pragma unroll
        for (int o = 16; o; o >>= 1) local += __shfl_down_sync(0xffffffffu, local, o);
        if (lane == 0) atomicAdd(&d_mask_sum, local);
    }
}

__device__ __forceinline__ uint32_t s2u(const void* p) {
    return (uint32_t)__cvta_generic_to_shared(p);
}
__device__ __forceinline__ __half2 tanh2(__half2 x) {
    uint32_t xi = *reinterpret_cast<uint32_t*>(&x), yi;
    asm("tanh.approx.f16x2 %0, %1;" : "=r"(yi) : "r"(xi));
    return *reinterpret_cast<__half2*>(&yi);
}
__device__ __forceinline__ __half2 sig2(__half2 x) {
    const __half2 hh = __float2half2_rn(0.5f);
    return __hfma2(tanh2(__hmul2(x, hh)), hh, hh);
}
__device__ __forceinline__ void barh(int id) {
    asm volatile("bar.sync %0, 256;" :: "r"(id) : "memory");
}

#define LDSM4(R, ADDR) \
    asm volatile("ldmatrix.sync.aligned.m8n8.x4.shared.b16 {%0,%1,%2,%3},[%4];" \
        : "=r"(R[0]),"=r"(R[1]),"=r"(R[2]),"=r"(R[3]) : "r"(ADDR))

#define MMAH(D, A, b0, b1) \
    asm volatile("mma.sync.aligned.m16n8k16.row.col.f32.f16.f16.f32 " \
        "{%0,%1,%2,%3},{%4,%5,%6,%7},{%8,%9},{%0,%1,%2,%3};" \
        : "+f"(D[0]),"+f"(D[1]),"+f"(D[2]),"+f"(D[3]) \
        : "r"(A[0]),"r"(A[1]),"r"(A[2]),"r"(A[3]),"r"(b0),"r"(b1))

// SMEM layout (bytes)
#define SM_WHH   0                                   // f16 [512][PITCH]  139264
#define SM_H     (SM_WHH + Gc * PITCH * 2)           // f16 2x[32][PITCH]  17408
#define SM_WL    (SM_H + 2 * NBLK * PITCH * 2)       // f16 [32][PITCH]     8704
#define SM_EW    (SM_WL + 32 * PITCH * 2)            // f16 [30][544]      32640
#define SM_LOG   (SM_EW + Vc * EWST * 2)             // f32 4x[32][36]     18432
#define SM_BL    (SM_LOG + 4 * LOGSTP * 4)           // f32 [32]             128
#define SM_TOK   (SM_BL + 32 * 4)                    // u8  [32][128]       4096
#define SM_TOTAL (SM_TOK + NBLK * Tc)                //                   220672

__global__ void __launch_bounds__(NTHR, 1)
lstm_kernel(const int* __restrict__ inpt,
            const float* __restrict__ h0,
            const float* __restrict__ c0,
            const float* __restrict__ mask,
            const float* __restrict__ W_hh,
            const float* __restrict__ W_lin,
            const float* __restrict__ b_lin) {
    extern __shared__ char smem[];
    __half*        whh_s = (__half*)(smem + SM_WHH);
    __half*        h_s   = (__half*)(smem + SM_H);     // 2 buffers of [32][PITCH]
    __half*        wl_s  = (__half*)(smem + SM_WL);
    __half*        ew_s  = (__half*)(smem + SM_EW);
    float*         log_s = (float*)(smem + SM_LOG);    // [pb2][kh2][32][36]
    float*         bl_s  = (float*)(smem + SM_BL);
    unsigned char* tok_s = (unsigned char*)(smem + SM_TOK);

    const int tid  = threadIdx.x;
    const int lane = tid & 31;
    const int wid  = tid >> 5;       // 0..15
    const int half = wid >> 3;       // 0..1 : independent batch-half
    const int hw   = wid & 7;        // warp within half
    const int gid  = lane >> 2;      // 0..7
    const int t4   = lane & 3;       // 0..3
    const int b0   = blockIdx.x * NBLK;
    const int bid  = 1 + half;       // named barrier id

    // ---- stage W_hh -> f16, permuted [gp][k] ----
    // g = gate*128 + u ; gp = 64*(u>>4) + 8*(2*((u>>2)&3) + (gate>>1)) + 2*(u&3) + (gate&1)
    for (int idx = tid; idx < Gc * Hc; idx += NTHR) {
        int g = idx >> 7, k = idx & 127;
        int u = g & 127, gate = g >> 7;
        int gp = 64 * (u >> 4) + 8 * (2 * ((u >> 2) & 3) + (gate >> 1))
               + 2 * (u & 3) + (gate & 1);
        whh_s[gp * PITCH + k] = __float2half(W_hh[idx]);
    }
    // ---- stage W_lin -> f16 [32 padded][k] ----
    for (int idx = tid; idx < 32 * Hc; idx += NTHR) {
        int v = idx >> 7, k = idx & 127;
        wl_s[v * PITCH + k] = (v < Vc) ? __float2half(W_lin[v * Hc + k])
                                       : __float2half(0.f);
    }
    // ---- stage h0 -> f16 buffer 0 ----
    for (int idx = tid; idx < NBLK * Hc; idx += NTHR) {
        int b = idx >> 7, u = idx & 127;
        h_s[b * PITCH + u] = __float2half(h0[(b0 + b) * Hc + u]);
    }
    // ---- EW packed table, biases, tokens ----
    {
        uint32_t* d32 = (uint32_t*)ew_s;
        const uint32_t* s32 = (const uint32_t*)d_EW2;
        for (int i = tid; i < Vc * EWST / 2; i += NTHR) d32[i] = s32[i];
    }
    if (tid < 32) bl_s[tid] = (tid < Vc) ? b_lin[tid] : 0.f;
    for (int idx = tid; idx < NBLK * Tc; idx += NTHR)
        tok_s[idx] = (unsigned char)inpt[b0 * Tc + idx];

    // ---- c state: cr[2p+rh], row = 16*half + gid + 8*rh, u = 16*hw + 4p + t4 ----
    float cr[8];
#pragma unroll
    for (int p = 0; p < 4; p++)
#pragma unroll
        for (int rh = 0; rh < 2; rh++)
            cr[2 * p + rh] =
                c0[(b0 + 16 * half + gid + 8 * rh) * Hc + 16 * hw + 4 * p + t4];

    // ---- ldmatrix address patterns ----
    const int m = lane >> 3;   // 0..3
    const uint32_t hs_base = s2u(h_s);
    // A (gates): rows 16*half + m16 tile
    const uint32_t aA_pat =
        (((16 * half + (m & 1) * 8 + (lane & 7)) * PITCH + (m >> 1) * 8) << 1);
    // B (gates): warp's n64 slice, 4 n16 quarters
    uint32_t aBq[4];
#pragma unroll
    for (int nq = 0; nq < 4; nq++)
        aBq[nq] = s2u(whh_s) +
            (((64 * hw + 16 * nq + (m >> 1) * 8 + (lane & 7)) * PITCH
              + (m & 1) * 8) << 1);
    const int ew_off = hw * 64 + t4 * 16;
    // logits split within half: kh = k-half, nl = n8 tile
    const int l_kh = hw & 1, l_nl = hw >> 1;
    const uint32_t aBL = s2u(wl_s) +
        (((8 * l_nl + (lane & 7)) * PITCH + l_kh * 64 + (lane >> 3) * 8) << 1);
    const uint32_t aAL_pat = aA_pat + (l_kh * 64 << 1);

    __syncthreads();   // staging visible to all

    // ---- cache B fragments for k0..31 (ks 0,1) : 32 regs ----
    uint32_t breg[2][16];
#pragma unroll
    for (int ks = 0; ks < 2; ks++)
#pragma unroll
        for (int nq = 0; nq < 4; nq++)
            LDSM4((&breg[ks][4 * nq]), aBq[nq] + ks * 32);

    float my_loss = 0.f;

    // logits of h-buffer hb -> partial pair pb (8 warps of this half)
    auto logits_pass = [&](int hb, int pb) {
        float lacc[4] = {0.f, 0.f, 0.f, 0.f};
        uint32_t aA = hs_base + hb * (HBE * 2) + aAL_pat;
        uint32_t B[8];
        LDSM4((&B[0]), aBL);
        LDSM4((&B[4]), aBL + 64);
#pragma unroll
        for (int c = 0; c < 4; c++) {
            uint32_t A[4];
            LDSM4(A, aA + c * 32);
            MMAH(lacc, A, B[2 * c], B[2 * c + 1]);
        }
        float* lout = log_s + (pb * 2 + l_kh) * LOGSTP;
        int r0 = (16 * half + gid) * 36 + 8 * l_nl + 2 * t4;
        *(float2*)&lout[r0]          = make_float2(lacc[0], lacc[1]);
        *(float2*)&lout[r0 + 8 * 36] = make_float2(lacc[2], lacc[3]);
    };

    // CE over logits pair pb for this half's rows; y = tok[:,ty], m = mask[:,tm]
    auto ce_pass = [&](int pb, int ty, int tm) {
        const float* lb0 = log_s + pb * 2 * LOGSTP;
        const float* lb1 = lb0 + LOGSTP;
#pragma unroll
        for (int bi = 0; bi < 2; bi++) {
            int row = 16 * half + 2 * hw + bi;
            float lg = (lane < Vc)
                ? (lb0[row * 36 + lane] + lb1[row * 36 + lane] + bl_s[lane])
                : -1e30f;
            float mx = lg;
#pragma unroll
            for (int o = 16; o; o >>= 1)
                mx = fmaxf(mx, __shfl_xor_sync(0xffffffffu, mx, o));
            float ex = (lane < Vc) ? __expf(lg - mx) : 0.f;
            float sm = ex;
#pragma unroll
            for (int o = 16; o; o >>= 1)
                sm += __shfl_xor_sync(0xffffffffu, sm, o);
            int y = (int)tok_s[row * Tc + ty];
            float ly = __shfl_sync(0xffffffffu, lg, y);
            if (lane == 0)
                my_loss += (mx + __logf(sm) - ly) * mask[(b0 + row) * Tc + tm];
        }
    };

#pragma unroll 1
    for (int t = 0; t < Tc - 1; t++) {
        const int cur = t & 1, nxt = cur ^ 1;
        barh(bid);   // this half's h / logits-partial writes visible

        // ---- accumulator init from packed EW ----
        int tok_lo = tok_s[(16 * half + gid) * Tc + t];
        int tok_hi = tok_s[(16 * half + gid + 8) * Tc + t];
        uint4 qa  = *(const uint4*)&ew_s[tok_lo * EWST + ew_off];
        uint4 qa2 = *(const uint4*)&ew_s[tok_lo * EWST + ew_off + 8];
        uint4 qb  = *(const uint4*)&ew_s[tok_hi * EWST + ew_off];
        uint4 qb2 = *(const uint4*)&ew_s[tok_hi * EWST + ew_off + 8];
        float a[8][4];
        {
            const uint32_t* pa  = &qa.x;
            const uint32_t* pa2 = &qa2.x;
            const uint32_t* pb  = &qb.x;
            const uint32_t* pb2 = &qb2.x;
#pragma unroll
            for (int nt = 0; nt < 4; nt++) {
                float2 f;
                f = __half22float2(*(__half2*)&pa[nt]);  a[nt][0]=f.x; a[nt][1]=f.y;
                f = __half22float2(*(__half2*)&pb[nt]);  a[nt][2]=f.x; a[nt][3]=f.y;
                f = __half22float2(*(__half2*)&pa2[nt]); a[nt+4][0]=f.x; a[nt+4][1]=f.y;
                f = __half22float2(*(__half2*)&pb2[nt]); a[nt+4][2]=f.x; a[nt+4][3]=f.y;
            }
        }

        // ---- gates MMA: A LDSM per ks; B from reg cache (ks<2) or LDSM ----
        const uint32_t aAc = hs_base + cur * (HBE * 2) + aA_pat;
#pragma unroll
        for (int ks = 0; ks < 8; ks++) {
            uint32_t A[4];
            LDSM4(A, aAc + ks * 32);
            if (ks < 2) {
#pragma unroll
                for (int nq = 0; nq < 4; nq++) {
                    MMAH(a[2 * nq],     A, breg[ks][4*nq],   breg[ks][4*nq+1]);
                    MMAH(a[2 * nq + 1], A, breg[ks][4*nq+2], breg[ks][4*nq+3]);
                }
            } else {
#pragma unroll
                for (int nq = 0; nq < 4; nq++) {
                    uint32_t B[4];
                    LDSM4(B, aBq[nq] + ks * 32);
                    MMAH(a[2 * nq],     A, B[0], B[1]);
                    MMAH(a[2 * nq + 1], A, B[2], B[3]);
                }
            }
        }

        // ---- independent work while MMAs retire ----
        if (t > 0) logits_pass(cur, cur);
        if (t > 1) ce_pass(nxt, t - 1, t - 2);

        // ---- LSTM cell: thread-local gates ----
        __half* hn = h_s + nxt * HBE;
#pragma unroll
        for (int p = 0; p < 4; p++) {
            __half2 i2 = __floats2half2_rn(a[2*p][0],   a[2*p][2]);
            __half2 f2 = __floats2half2_rn(a[2*p][1],   a[2*p][3]);
            __half2 g2 = __floats2half2_rn(a[2*p+1][0], a[2*p+1][2]);
            __half2 o2 = __floats2half2_rn(a[2*p+1][1], a[2*p+1][3]);
            __half2 si = sig2(i2), sf = sig2(f2), so = sig2(o2);
            __half2 tg = tanh2(g2);
            __half2 it = __hmul2(si, tg);
            float c2a = fmaf(__low2float(sf),  cr[2*p],   __low2float(it));
            float c2b = fmaf(__high2float(sf), cr[2*p+1], __high2float(it));
            cr[2*p] = c2a; cr[2*p+1] = c2b;
            __half2 hh = __hmul2(so, tanh2(__floats2half2_rn(c2a, c2b)));
            int u = 16 * hw + 4 * p + t4;
            hn[(16 * half + gid) * PITCH + u]     = __low2half(hh);
            hn[(16 * half + gid + 8) * PITCH + u] = __high2half(hh);
        }
    }

    // ---- tail (per half): consume logits(h_126); score + consume h_127 ----
    barh(bid);
    ce_pass(0, Tc - 2, Tc - 3);   // logits(h_126) in pair 0
    logits_pass(1, 1);            // h_127 lives in buffer 1 -> pair 1
    barh(bid);
    ce_pass(1, Tc - 1, Tc - 2);

    // ---- block loss reduction ----
#pragma unroll
    for (int o = 16; o; o >>= 1)
        my_loss += __shfl_xor_sync(0xffffffffu, my_loss, o);
    __shared__ float wsum[16];
    if (lane == 0) wsum[wid] = my_loss;
    __syncthreads();
    if (wid == 0) {
        float v = (lane < 16) ? wsum[lane] : 0.f;
#pragma unroll
        for (int o = 8; o; o >>= 1)
            v += __shfl_xor_sync(0xffffffffu, v, o);
        if (lane == 0) atomicAdd(&d_loss_sum, (double)v);
    }
}

__global__ void finalize_kernel(float* out) {
    out[0] = (float)(d_loss_sum / d_mask_sum);
}

extern "C" void kernel_launch(void* const* d_in, const int* in_sizes, int n_in,
                              void* d_out, int out_size) {
    const int*   inpt  = (const int*)d_in[0];
    const float* h0    = (const float*)d_in[1];
    const float* c0    = (const float*)d_in[2];
    const float* mask  = (const float*)d_in[3];
    // d_in[4] = beta (unused)
    const float* emb   = (const float*)d_in[5];
    const float* W_ih  = (const float*)d_in[6];
    const float* b_ih  = (const float*)d_in[7];
    const float* W_hh  = (const float*)d_in[8];
    const float* b_hh  = (const float*)d_in[9];
    const float* W_lin = (const float*)d_in[10];
    const float* b_lin = (const float*)d_in[11];
    float* out = (float*)d_out;

    cudaFuncSetAttribute(lstm_kernel,
                         cudaFuncAttributeMaxDynamicSharedMemorySize, SM_TOTAL);

    zero_kernel<<<1, 1>>>();
    mask_sum_kernel<<<256, 256>>>(mask, Bc * Tc);
    ew_kernel<<<Vc, NTHR>>>(emb, W_ih, b_ih, b_hh);
    lstm_kernel<<<Bc / NBLK, NTHR, SM_TOTAL>>>(inpt, h0, c0, mask,
                                               W_hh, W_lin, b_lin);
    finalize_kernel<<<1, 1>>>(out);
}

// round 7
// speedup vs baseline: 10.2484x; 1.0097x over previous
#include <cuda_runtime.h>
#include <cuda_fp16.h>
#include <math.h>
#include <stdint.h>

// Problem dims
#define Bc 4096
#define Tc 128
#define Vc 30
#define Ec 256
#define Hc 128
#define Gc 512      // 4*H
#define NBLK 32     // batch rows per CTA (two independent halves of 16)
#define NTHR 512    // 16 warps
#define PITCH 136   // f16 elements per row -> conflict-free ldmatrix
#define HBE  (NBLK * PITCH)        // h buffer stride (elements)
#define EWST 544                   // halves per vocab row (512 + pad)
#define LOGSTP 1152                // floats per logits partial buffer (32*36)

// Scratch
__device__ __half d_EW2[Vc * EWST];
__device__ double d_loss_sum;
__device__ double d_mask_sum;

__global__ void zero_kernel() { d_loss_sum = 0.0; d_mask_sum = 0.0; }

// Storage idx in [0,512): hw=idx>>6, t4=(idx>>4)&3, e=idx&15, nt=e>>1, j=e&1
//   p = nt>>1, gb = nt&1, gate = 2*gb + j, u = 16*hw + 4*p + t4, g = gate*128+u
__global__ void ew_kernel(const float* __restrict__ emb,
                          const float* __restrict__ W_ih,
                          const float* __restrict__ b_ih,
                          const float* __restrict__ b_hh) {
    __shared__ float ev[Ec];
    int v = blockIdx.x;
    int idx = threadIdx.x;
    int hw = idx >> 6, t4p = (idx >> 4) & 3, e = idx & 15;
    int nt = e >> 1, j = e & 1;
    int p = nt >> 1, gb = nt & 1;
    int gate = 2 * gb + j;
    int u = 16 * hw + 4 * p + t4p;
    int g = gate * Hc + u;
    for (int ee = threadIdx.x; ee < Ec; ee += blockDim.x) ev[ee] = emb[v * Ec + ee];
    __syncthreads();
    float acc = b_ih[g] + b_hh[g];
    const float* w = W_ih + g * Ec;
#pragma unroll 8
    for (int ee = 0; ee < Ec; ee++) acc += w[ee] * ev[ee];
    d_EW2[v * EWST + idx] = __float2half(acc);
}

__global__ void mask_sum_kernel(const float* __restrict__ mask, int n) {
    double local = 0.0;
    for (int i = blockIdx.x * blockDim.x + threadIdx.x; i < n;
         i += gridDim.x * blockDim.x)
        local += (double)mask[i];
#pragma unroll
    for (int o = 16; o; o >>= 1) local += __shfl_down_sync(0xffffffffu, local, o);
    __shared__ double ws[32];
    int lane = threadIdx.x & 31, w = threadIdx.x >> 5;
    if (lane == 0) ws[w] = local;
    __syncthreads();
    if (w == 0) {
        local = (lane < (int)(blockDim.x >> 5)) ? ws[lane] : 0.0;
#pragma unroll
        for (int o = 16; o; o >>= 1) local += __shfl_down_sync(0xffffffffu, local, o);
        if (lane == 0) atomicAdd(&d_mask_sum, local);
    }
}

__device__ __forceinline__ uint32_t s2u(const void* p) {
    return (uint32_t)__cvta_generic_to_shared(p);
}
__device__ __forceinline__ __half2 tanh2(__half2 x) {
    uint32_t xi = *reinterpret_cast<uint32_t*>(&x), yi;
    asm("tanh.approx.f16x2 %0, %1;" : "=r"(yi) : "r"(xi));
    return *reinterpret_cast<__half2*>(&yi);
}
__device__ __forceinline__ __half2 sig2(__half2 x) {
    const __half2 hh = __float2half2_rn(0.5f);
    return __hfma2(tanh2(__hmul2(x, hh)), hh, hh);
}
__device__ __forceinline__ void barh(int id) {
    asm volatile("bar.sync %0, 256;" :: "r"(id) : "memory");
}

#define LDSM4(R, ADDR) \
    asm volatile("ldmatrix.sync.aligned.m8n8.x4.shared.b16 {%0,%1,%2,%3},[%4];" \
        : "=r"(R[0]),"=r"(R[1]),"=r"(R[2]),"=r"(R[3]) : "r"(ADDR))

// f16-accumulator gates MMA
#define MMAH16(D, A, b0, b1) \
    asm volatile("mma.sync.aligned.m16n8k16.row.col.f16.f16.f16.f16 " \
        "{%0,%1},{%2,%3,%4,%5},{%6,%7},{%0,%1};" \
        : "+r"(D[0]),"+r"(D[1]) \
        : "r"(A[0]),"r"(A[1]),"r"(A[2]),"r"(A[3]),"r"(b0),"r"(b1))

// f32-accumulator logits MMA
#define MMAH(D, A, b0, b1) \
    asm volatile("mma.sync.aligned.m16n8k16.row.col.f32.f16.f16.f32 " \
        "{%0,%1,%2,%3},{%4,%5,%6,%7},{%8,%9},{%0,%1,%2,%3};" \
        : "+f"(D[0]),"+f"(D[1]),"+f"(D[2]),"+f"(D[3]) \
        : "r"(A[0]),"r"(A[1]),"r"(A[2]),"r"(A[3]),"r"(b0),"r"(b1))

// SMEM layout (bytes)
#define SM_WHH   0                                   // f16 [512][PITCH]  139264
#define SM_H     (SM_WHH + Gc * PITCH * 2)           // f16 2x[32][PITCH]  17408
#define SM_WL    (SM_H + 2 * NBLK * PITCH * 2)       // f16 [32][PITCH]     8704
#define SM_EW    (SM_WL + 32 * PITCH * 2)            // f16 [30][544]      32640
#define SM_LOG   (SM_EW + Vc * EWST * 2)             // f32 4x[32][36]     18432
#define SM_BL    (SM_LOG + 4 * LOGSTP * 4)           // f32 [32]             128
#define SM_TOK   (SM_BL + 32 * 4)                    // u8  [32][128]       4096
#define SM_TOTAL (SM_TOK + NBLK * Tc)                //                   220672

__global__ void __launch_bounds__(NTHR, 1)
lstm_kernel(const int* __restrict__ inpt,
            const float* __restrict__ h0,
            const float* __restrict__ c0,
            const float* __restrict__ mask,
            const float* __restrict__ W_hh,
            const float* __restrict__ W_lin,
            const float* __restrict__ b_lin) {
    extern __shared__ char smem[];
    __half*        whh_s = (__half*)(smem + SM_WHH);
    __half*        h_s   = (__half*)(smem + SM_H);     // 2 buffers of [32][PITCH]
    __half*        wl_s  = (__half*)(smem + SM_WL);
    __half*        ew_s  = (__half*)(smem + SM_EW);
    float*         log_s = (float*)(smem + SM_LOG);    // [pb2][kh2][32][36]
    float*         bl_s  = (float*)(smem + SM_BL);
    unsigned char* tok_s = (unsigned char*)(smem + SM_TOK);

    const int tid  = threadIdx.x;
    const int lane = tid & 31;
    const int wid  = tid >> 5;       // 0..15
    const int half = wid >> 3;       // 0..1 : independent batch-half
    const int hw   = wid & 7;        // warp within half
    const int gid  = lane >> 2;      // 0..7
    const int t4   = lane & 3;       // 0..3
    const int b0   = blockIdx.x * NBLK;
    const int bid  = 1 + half;       // named barrier id

    // ---- stage W_hh -> f16, permuted [gp][k] ----
    for (int idx = tid; idx < Gc * Hc; idx += NTHR) {
        int g = idx >> 7, k = idx & 127;
        int u = g & 127, gate = g >> 7;
        int gp = 64 * (u >> 4) + 8 * (2 * ((u >> 2) & 3) + (gate >> 1))
               + 2 * (u & 3) + (gate & 1);
        whh_s[gp * PITCH + k] = __float2half(W_hh[idx]);
    }
    // ---- stage W_lin -> f16 [32 padded][k] ----
    for (int idx = tid; idx < 32 * Hc; idx += NTHR) {
        int v = idx >> 7, k = idx & 127;
        wl_s[v * PITCH + k] = (v < Vc) ? __float2half(W_lin[v * Hc + k])
                                       : __float2half(0.f);
    }
    // ---- stage h0 -> f16 buffer 0 ----
    for (int idx = tid; idx < NBLK * Hc; idx += NTHR) {
        int b = idx >> 7, u = idx & 127;
        h_s[b * PITCH + u] = __float2half(h0[(b0 + b) * Hc + u]);
    }
    // ---- EW packed table, biases, tokens ----
    {
        uint32_t* d32 = (uint32_t*)ew_s;
        const uint32_t* s32 = (const uint32_t*)d_EW2;
        for (int i = tid; i < Vc * EWST / 2; i += NTHR) d32[i] = s32[i];
    }
    if (tid < 32) bl_s[tid] = (tid < Vc) ? b_lin[tid] : 0.f;
    for (int idx = tid; idx < NBLK * Tc; idx += NTHR)
        tok_s[idx] = (unsigned char)inpt[b0 * Tc + idx];

    // ---- c state (fp32): cr[2p+rh], row = 16*half+gid+8rh, u = 16hw+4p+t4 ----
    float cr[8];
#pragma unroll
    for (int p = 0; p < 4; p++)
#pragma unroll
        for (int rh = 0; rh < 2; rh++)
            cr[2 * p + rh] =
                c0[(b0 + 16 * half + gid + 8 * rh) * Hc + 16 * hw + 4 * p + t4];

    // ---- ldmatrix address patterns ----
    const int m = lane >> 3;   // 0..3
    const uint32_t hs_base = s2u(h_s);
    const uint32_t aA_pat =
        (((16 * half + (m & 1) * 8 + (lane & 7)) * PITCH + (m >> 1) * 8) << 1);
    const uint32_t aB_base = s2u(whh_s) +
        (((64 * hw + (m >> 1) * 8 + (lane & 7)) * PITCH + (m & 1) * 8) << 1);
#define ABQ(nq) (aB_base + (uint32_t)((nq) * (16 * PITCH * 2)))
    const int ew_off = hw * 64 + t4 * 16;
    const int l_kh = hw & 1, l_nl = hw >> 1;
    const uint32_t aBL = s2u(wl_s) +
        (((8 * l_nl + (lane & 7)) * PITCH + l_kh * 64 + (lane >> 3) * 8) << 1);
    const uint32_t aAL_pat = aA_pat + (l_kh * 64 << 1);

    __syncthreads();   // staging visible to all

    // ---- cache B fragments for ks 0..3 : 64 regs ----
    uint32_t breg[4][16];
#pragma unroll
    for (int ks = 0; ks < 4; ks++)
#pragma unroll
        for (int nq = 0; nq < 4; nq++)
            LDSM4((&breg[ks][4 * nq]), ABQ(nq) + ks * 32);

    float my_loss = 0.f;

    // logits of h-buffer hb -> partial pair pb (8 warps of this half)
    auto logits_pass = [&](int hb, int pb) {
        float lacc[4] = {0.f, 0.f, 0.f, 0.f};
        uint32_t aA = hs_base + hb * (HBE * 2) + aAL_pat;
        uint32_t B[8];
        LDSM4((&B[0]), aBL);
        LDSM4((&B[4]), aBL + 64);
#pragma unroll
        for (int c = 0; c < 4; c++) {
            uint32_t A[4];
            LDSM4(A, aA + c * 32);
            MMAH(lacc, A, B[2 * c], B[2 * c + 1]);
        }
        float* lout = log_s + (pb * 2 + l_kh) * LOGSTP;
        int r0 = (16 * half + gid) * 36 + 8 * l_nl + 2 * t4;
        *(float2*)&lout[r0]          = make_float2(lacc[0], lacc[1]);
        *(float2*)&lout[r0 + 8 * 36] = make_float2(lacc[2], lacc[3]);
    };

    // CE over logits pair pb for this half's rows; y = tok[:,ty], m = mask[:,tm]
    auto ce_pass = [&](int pb, int ty, int tm) {
        const float* lb0 = log_s + pb * 2 * LOGSTP;
        const float* lb1 = lb0 + LOGSTP;
#pragma unroll
        for (int bi = 0; bi < 2; bi++) {
            int row = 16 * half + 2 * hw + bi;
            float lg = (lane < Vc)
                ? (lb0[row * 36 + lane] + lb1[row * 36 + lane] + bl_s[lane])
                : -1e30f;
            float mx = lg;
#pragma unroll
            for (int o = 16; o; o >>= 1)
                mx = fmaxf(mx, __shfl_xor_sync(0xffffffffu, mx, o));
            float ex = (lane < Vc) ? __expf(lg - mx) : 0.f;
            float sm = ex;
#pragma unroll
            for (int o = 16; o; o >>= 1)
                sm += __shfl_xor_sync(0xffffffffu, sm, o);
            int y = (int)tok_s[row * Tc + ty];
            float ly = __shfl_sync(0xffffffffu, lg, y);
            if (lane == 0)
                my_loss += (mx + __logf(sm) - ly) * mask[(b0 + row) * Tc + tm];
        }
    };

#pragma unroll 1
    for (int t = 0; t < Tc - 1; t++) {
        const int cur = t & 1, nxt = cur ^ 1;
        barh(bid);   // this half's h / logits-partial writes visible

        // ---- accumulator init: packed EW words ARE f16-D fragments ----
        int tok_lo = tok_s[(16 * half + gid) * Tc + t];
        int tok_hi = tok_s[(16 * half + gid + 8) * Tc + t];
        uint4 qa  = *(const uint4*)&ew_s[tok_lo * EWST + ew_off];
        uint4 qa2 = *(const uint4*)&ew_s[tok_lo * EWST + ew_off + 8];
        uint4 qb  = *(const uint4*)&ew_s[tok_hi * EWST + ew_off];
        uint4 qb2 = *(const uint4*)&ew_s[tok_hi * EWST + ew_off + 8];
        uint32_t d[8][2];
        {
            const uint32_t* pa  = &qa.x;
            const uint32_t* pa2 = &qa2.x;
            const uint32_t* pb  = &qb.x;
            const uint32_t* pb2 = &qb2.x;
#pragma unroll
            for (int nt = 0; nt < 4; nt++) {
                d[nt][0]     = pa[nt];  d[nt][1]     = pb[nt];
                d[nt + 4][0] = pa2[nt]; d[nt + 4][1] = pb2[nt];
            }
        }

        // ---- gates MMA (f16 D): A LDSM per ks; B reg cache ks<4, LDSM ks>=4 ----
        const uint32_t aAc = hs_base + cur * (HBE * 2) + aA_pat;
#pragma unroll
        for (int ks = 0; ks < 8; ks++) {
            uint32_t A[4];
            LDSM4(A, aAc + ks * 32);
            if (ks < 4) {
#pragma unroll
                for (int nq = 0; nq < 4; nq++) {
                    MMAH16(d[2 * nq],     A, breg[ks][4*nq],   breg[ks][4*nq+1]);
                    MMAH16(d[2 * nq + 1], A, breg[ks][4*nq+2], breg[ks][4*nq+3]);
                }
            } else {
#pragma unroll
                for (int nq = 0; nq < 4; nq++) {
                    uint32_t B[4];
                    LDSM4(B, ABQ(nq) + ks * 32);
                    MMAH16(d[2 * nq],     A, B[0], B[1]);
                    MMAH16(d[2 * nq + 1], A, B[2], B[3]);
                }
            }
        }

        // ---- independent work while MMAs retire ----
        if (t > 0) logits_pass(cur, cur);
        if (t > 1) ce_pass(nxt, t - 1, t - 2);

        // ---- LSTM cell: gates already packed as half2 (i,f)/(g,o) pairs ----
        __half* hn = h_s + nxt * HBE;
#pragma unroll
        for (int p = 0; p < 4; p++) {
            __half2 rif_lo = *(__half2*)&d[2 * p][0];      // (i,f) row gid
            __half2 rif_hi = *(__half2*)&d[2 * p][1];      // (i,f) row gid+8
            __half2 rgo_lo = *(__half2*)&d[2 * p + 1][0];  // (g,o) row gid
            __half2 rgo_hi = *(__half2*)&d[2 * p + 1][1];  // (g,o) row gid+8
            __half2 i2 = __lows2half2(rif_lo, rif_hi);
            __half2 f2 = __highs2half2(rif_lo, rif_hi);
            __half2 g2 = __lows2half2(rgo_lo, rgo_hi);
            __half2 o2 = __highs2half2(rgo_lo, rgo_hi);
            __half2 si = sig2(i2), sf = sig2(f2), so = sig2(o2);
            __half2 tg = tanh2(g2);
            __half2 it = __hmul2(si, tg);
            float c2a = fmaf(__low2float(sf),  cr[2*p],   __low2float(it));
            float c2b = fmaf(__high2float(sf), cr[2*p+1], __high2float(it));
            cr[2*p] = c2a; cr[2*p+1] = c2b;
            __half2 hh = __hmul2(so, tanh2(__floats2half2_rn(c2a, c2b)));
            int u = 16 * hw + 4 * p + t4;
            hn[(16 * half + gid) * PITCH + u]     = __low2half(hh);
            hn[(16 * half + gid + 8) * PITCH + u] = __high2half(hh);
        }
    }

    // ---- tail (per half): consume logits(h_126); score + consume h_127 ----
    barh(bid);
    ce_pass(0, Tc - 2, Tc - 3);   // logits(h_126) in pair 0
    logits_pass(1, 1);            // h_127 lives in buffer 1 -> pair 1
    barh(bid);
    ce_pass(1, Tc - 1, Tc - 2);

    // ---- block loss reduction ----
#pragma unroll
    for (int o = 16; o; o >>= 1)
        my_loss += __shfl_xor_sync(0xffffffffu, my_loss, o);
    __shared__ float wsum[16];
    if (lane == 0) wsum[wid] = my_loss;
    __syncthreads();
    if (wid == 0) {
        float v = (lane < 16) ? wsum[lane] : 0.f;
#pragma unroll
        for (int o = 8; o; o >>= 1)
            v += __shfl_xor_sync(0xffffffffu, v, o);
        if (lane == 0) atomicAdd(&d_loss_sum, (double)v);
    }
}

__global__ void finalize_kernel(float* out) {
    out[0] = (float)(d_loss_sum / d_mask_sum);
}

extern "C" void kernel_launch(void* const* d_in, const int* in_sizes, int n_in,
                              void* d_out, int out_size) {
    const int*   inpt  = (const int*)d_in[0];
    const float* h0    = (const float*)d_in[1];
    const float* c0    = (const float*)d_in[2];
    const float* mask  = (const float*)d_in[3];
    // d_in[4] = beta (unused)
    const float* emb   = (const float*)d_in[5];
    const float* W_ih  = (const float*)d_in[6];
    const float* b_ih  = (const float*)d_in[7];
    const float* W_hh  = (const float*)d_in[8];
    const float* b_hh  = (const float*)d_in[9];
    const float* W_lin = (const float*)d_in[10];
    const float* b_lin = (const float*)d_in[11];
    float* out = (float*)d_out;

    cudaFuncSetAttribute(lstm_kernel,
                         cudaFuncAttributeMaxDynamicSharedMemorySize, SM_TOTAL);

    zero_kernel<<<1, 1>>>();
    mask_sum_kernel<<<256, 256>>>(mask, Bc * Tc);
    ew_kernel<<<Vc, NTHR>>>(emb, W_ih, b_ih, b_hh);
    lstm_kernel<<<Bc / NBLK, NTHR, SM_TOTAL>>>(inpt, h0, c0, mask,
                                               W_hh, W_lin, b_lin);
    finalize_kernel<<<1, 1>>>(out);
}

// round 8
// speedup vs baseline: 10.3842x; 1.0133x over previous
#include <cuda_runtime.h>
#include <cuda_fp16.h>
#include <math.h>
#include <stdint.h>

// Problem dims
#define Bc 4096
#define Tc 128
#define Vc 30
#define Ec 256
#define Hc 128
#define Gc 512      // 4*H
#define NBLK 32     // batch rows per CTA (two independent halves of 16)
#define NTHR 512    // 16 warps
#define PITCH 136   // f16 elements per row -> conflict-free ldmatrix
#define HBE  (NBLK * PITCH)        // h buffer stride (elements)
#define EWST 544                   // halves per vocab row (512 + pad)
#define KQH  1152                  // halves per (kq) logits slab: 32*36
#define LOGH (4 * KQH)             // halves per parity: 4 kq slabs

// Scratch
__device__ __half d_EW2[Vc * EWST];
__device__ double d_loss_sum;
__device__ double d_mask_sum;

__global__ void zero_kernel() { d_loss_sum = 0.0; d_mask_sum = 0.0; }

// Storage idx in [0,512): hw=idx>>6, t4=(idx>>4)&3, e=idx&15, nt=e>>1, j=e&1
//   p = nt>>1, gb = nt&1, gate = 2*gb + j, u = 16*hw + 4*t4 + p, g = gate*128+u
__global__ void ew_kernel(const float* __restrict__ emb,
                          const float* __restrict__ W_ih,
                          const float* __restrict__ b_ih,
                          const float* __restrict__ b_hh) {
    __shared__ float ev[Ec];
    int v = blockIdx.x;
    int idx = threadIdx.x;
    int hw = idx >> 6, t4p = (idx >> 4) & 3, e = idx & 15;
    int nt = e >> 1, j = e & 1;
    int p = nt >> 1, gb = nt & 1;
    int gate = 2 * gb + j;
    int u = 16 * hw + 4 * t4p + p;
    int g = gate * Hc + u;
    for (int ee = threadIdx.x; ee < Ec; ee += blockDim.x) ev[ee] = emb[v * Ec + ee];
    __syncthreads();
    float acc = b_ih[g] + b_hh[g];
    const float* w = W_ih + g * Ec;
#pragma unroll 8
    for (int ee = 0; ee < Ec; ee++) acc += w[ee] * ev[ee];
    d_EW2[v * EWST + idx] = __float2half(acc);
}

__global__ void mask_sum_kernel(const float* __restrict__ mask, int n) {
    double local = 0.0;
    for (int i = blockIdx.x * blockDim.x + threadIdx.x; i < n;
         i += gridDim.x * blockDim.x)
        local += (double)mask[i];
#pragma unroll
    for (int o = 16; o; o >>= 1) local += __shfl_down_sync(0xffffffffu, local, o);
    __shared__ double ws[32];
    int lane = threadIdx.x & 31, w = threadIdx.x >> 5;
    if (lane == 0) ws[w] = local;
    __syncthreads();
    if (w == 0) {
        local = (lane < (int)(blockDim.x >> 5)) ? ws[lane] : 0.0;
#pragma unroll
        for (int o = 16; o; o >>= 1) local += __shfl_down_sync(0xffffffffu, local, o);
        if (lane == 0) atomicAdd(&d_mask_sum, local);
    }
}

__device__ __forceinline__ uint32_t s2u(const void* p) {
    return (uint32_t)__cvta_generic_to_shared(p);
}
__device__ __forceinline__ __half2 tanh2(__half2 x) {
    uint32_t xi = *reinterpret_cast<uint32_t*>(&x), yi;
    asm("tanh.approx.f16x2 %0, %1;" : "=r"(yi) : "r"(xi));
    return *reinterpret_cast<__half2*>(&yi);
}
__device__ __forceinline__ __half2 sig2(__half2 x) {
    const __half2 hh = __float2half2_rn(0.5f);
    return __hfma2(tanh2(__hmul2(x, hh)), hh, hh);
}
__device__ __forceinline__ void barh(int id) {
    asm volatile("bar.sync %0, 256;" :: "r"(id) : "memory");
}

#define LDSM4(R, ADDR) \
    asm volatile("ldmatrix.sync.aligned.m8n8.x4.shared.b16 {%0,%1,%2,%3},[%4];" \
        : "=r"(R[0]),"=r"(R[1]),"=r"(R[2]),"=r"(R[3]) : "r"(ADDR))

// f16-accumulator MMA
#define MMAH16(D, A, b0, b1) \
    asm volatile("mma.sync.aligned.m16n8k16.row.col.f16.f16.f16.f16 " \
        "{%0,%1},{%2,%3,%4,%5},{%6,%7},{%0,%1};" \
        : "+r"(D[0]),"+r"(D[1]) \
        : "r"(A[0]),"r"(A[1]),"r"(A[2]),"r"(A[3]),"r"(b0),"r"(b1))

// SMEM layout (bytes)
#define SM_WHH   0                                   // f16 [512][PITCH]  139264
#define SM_H     (SM_WHH + Gc * PITCH * 2)           // f16 2x[32][PITCH]  17408
#define SM_WL    (SM_H + 2 * NBLK * PITCH * 2)       // f16 [32][PITCH]     8704
#define SM_EW    (SM_WL + 32 * PITCH * 2)            // f16 [30][544]      32640
#define SM_LOGH  (SM_EW + Vc * EWST * 2)             // f16 2x4x[32][36]   18432
#define SM_BL    (SM_LOGH + 2 * LOGH * 2)            // f32 [32]             128
#define SM_TOK   (SM_BL + 32 * 4)                    // u8  [32][128]       4096
#define SM_TOTAL (SM_TOK + NBLK * Tc)                //                   220672

__global__ void __launch_bounds__(NTHR, 1)
lstm_kernel(const int* __restrict__ inpt,
            const float* __restrict__ h0,
            const float* __restrict__ c0,
            const float* __restrict__ mask,
            const float* __restrict__ W_hh,
            const float* __restrict__ W_lin,
            const float* __restrict__ b_lin) {
    extern __shared__ char smem[];
    __half*        whh_s = (__half*)(smem + SM_WHH);
    __half*        h_s   = (__half*)(smem + SM_H);     // 2 buffers of [32][PITCH]
    __half*        wl_s  = (__half*)(smem + SM_WL);
    __half*        ew_s  = (__half*)(smem + SM_EW);
    __half*        log_h = (__half*)(smem + SM_LOGH);  // [par2][kq4][32][36]
    float*         bl_s  = (float*)(smem + SM_BL);
    unsigned char* tok_s = (unsigned char*)(smem + SM_TOK);

    const int tid  = threadIdx.x;
    const int lane = tid & 31;
    const int wid  = tid >> 5;       // 0..15
    const int half = wid >> 3;       // 0..1 : independent batch-half
    const int hw   = wid & 7;        // warp within half
    const int gid  = lane >> 2;      // 0..7
    const int t4   = lane & 3;       // 0..3
    const int b0   = blockIdx.x * NBLK;
    const int bid  = 1 + half;       // named barrier id

    // ---- stage W_hh -> f16, permuted [gp][k] ----
    // u = 16hw + 4t4 + p ; gp = 64*(u>>4) + 8*(2*(u&3) + (gate>>1)) + 2*((u>>2)&3) + (gate&1)
    for (int idx = tid; idx < Gc * Hc; idx += NTHR) {
        int g = idx >> 7, k = idx & 127;
        int u = g & 127, gate = g >> 7;
        int gp = 64 * (u >> 4) + 8 * (2 * (u & 3) + (gate >> 1))
               + 2 * ((u >> 2) & 3) + (gate & 1);
        whh_s[gp * PITCH + k] = __float2half(W_hh[idx]);
    }
    // ---- stage W_lin -> f16 [32 padded][k] ----
    for (int idx = tid; idx < 32 * Hc; idx += NTHR) {
        int v = idx >> 7, k = idx & 127;
        wl_s[v * PITCH + k] = (v < Vc) ? __float2half(W_lin[v * Hc + k])
                                       : __float2half(0.f);
    }
    // ---- stage h0 -> f16 buffer 0 ----
    for (int idx = tid; idx < NBLK * Hc; idx += NTHR) {
        int b = idx >> 7, u = idx & 127;
        h_s[b * PITCH + u] = __float2half(h0[(b0 + b) * Hc + u]);
    }
    // ---- EW packed table, biases, tokens ----
    {
        uint32_t* d32 = (uint32_t*)ew_s;
        const uint32_t* s32 = (const uint32_t*)d_EW2;
        for (int i = tid; i < Vc * EWST / 2; i += NTHR) d32[i] = s32[i];
    }
    if (tid < 32) bl_s[tid] = (tid < Vc) ? b_lin[tid] : 0.f;
    for (int idx = tid; idx < NBLK * Tc; idx += NTHR)
        tok_s[idx] = (unsigned char)inpt[b0 * Tc + idx];

    // ---- c state (fp32): cr[2p+rh], row = 16*half+gid+8rh, u = 16hw+4t4+p ----
    float cr[8];
#pragma unroll
    for (int p = 0; p < 4; p++)
#pragma unroll
        for (int rh = 0; rh < 2; rh++)
            cr[2 * p + rh] =
                c0[(b0 + 16 * half + gid + 8 * rh) * Hc + 16 * hw + 4 * t4 + p];

    // ---- ldmatrix address patterns ----
    const int m = lane >> 3;   // 0..3
    const uint32_t hs_base = s2u(h_s);
    const uint32_t aA_pat =
        (((16 * half + (m & 1) * 8 + (lane & 7)) * PITCH + (m >> 1) * 8) << 1);
    const uint32_t aB_base = s2u(whh_s) +
        (((64 * hw + (m >> 1) * 8 + (lane & 7)) * PITCH + (m & 1) * 8) << 1);
#define ABQ(nq) (aB_base + (uint32_t)((nq) * (16 * PITCH * 2)))
    const int ew_off = hw * 64 + t4 * 16;
    // merged logits: unit = (v-half l_nh, k-quarter l_kq)
    const int l_nh = hw >> 2, l_kq = hw & 3;
    const uint32_t aBLm = s2u(wl_s) +
        (((16 * l_nh + (m >> 1) * 8 + (lane & 7)) * PITCH + (m & 1) * 8) << 1);
    const int hst_base = 16 * hw + 4 * t4;   // contiguous 4-u store base

    __syncthreads();   // staging visible to all

    // ---- cache B fragments for ks 0..3 : 64 regs ----
    uint32_t breg[4][16];
#pragma unroll
    for (int ks = 0; ks < 4; ks++)
#pragma unroll
        for (int nq = 0; nq < 4; nq++)
            LDSM4((&breg[ks][4 * nq]), ABQ(nq) + ks * 32);

    float my_loss = 0.f;

    // store this warp's f16 logits partials to parity buffer
    auto store_dlog = [&](uint32_t dl0[2], uint32_t dl1[2], int par) {
        __half* lout = log_h + par * LOGH + l_kq * KQH + (16 * half) * 36;
        int v0 = 16 * l_nh + 2 * t4;
        *(uint32_t*)&lout[gid * 36 + v0]           = dl0[0];
        *(uint32_t*)&lout[(gid + 8) * 36 + v0]     = dl0[1];
        *(uint32_t*)&lout[gid * 36 + v0 + 8]       = dl1[0];
        *(uint32_t*)&lout[(gid + 8) * 36 + v0 + 8] = dl1[1];
    };

    // CE over parity pb for this half's rows; y = tok[:,ty], m = mask[:,tm]
    auto ce_pass = [&](int pb, int ty, int tm) {
#pragma unroll
        for (int bi = 0; bi < 2; bi++) {
            int row = 16 * half + 2 * hw + bi;
            const __half* lb = log_h + pb * LOGH + row * 36;
            float lg;
            if (lane < Vc) {
                lg = bl_s[lane]
                   + __half2float(lb[lane])
                   + __half2float(lb[KQH + lane])
                   + __half2float(lb[2 * KQH + lane])
                   + __half2float(lb[3 * KQH + lane]);
            } else lg = -1e30f;
            float mx = lg;
#pragma unroll
            for (int o = 16; o; o >>= 1)
                mx = fmaxf(mx, __shfl_xor_sync(0xffffffffu, mx, o));
            float ex = (lane < Vc) ? __expf(lg - mx) : 0.f;
            float sm = ex;
#pragma unroll
            for (int o = 16; o; o >>= 1)
                sm += __shfl_xor_sync(0xffffffffu, sm, o);
            int y = (int)tok_s[row * Tc + ty];
            float ly = __shfl_sync(0xffffffffu, lg, y);
            if (lane == 0)
                my_loss += (mx + __logf(sm) - ly) * mask[(b0 + row) * Tc + tm];
        }
    };

#pragma unroll 1
    for (int t = 0; t < Tc - 1; t++) {
        const int cur = t & 1, nxt = cur ^ 1;

        // ---- prefetch EW + tokens (static tables; hides under barrier) ----
        int tok_lo = tok_s[(16 * half + gid) * Tc + t];
        int tok_hi = tok_s[(16 * half + gid + 8) * Tc + t];
        uint4 qa  = *(const uint4*)&ew_s[tok_lo * EWST + ew_off];
        uint4 qa2 = *(const uint4*)&ew_s[tok_lo * EWST + ew_off + 8];
        uint4 qb  = *(const uint4*)&ew_s[tok_hi * EWST + ew_off];
        uint4 qb2 = *(const uint4*)&ew_s[tok_hi * EWST + ew_off + 8];

        barh(bid);   // this half's h / logits writes visible

        // ---- accumulator init: packed EW words ARE f16-D fragments ----
        uint32_t d[8][2];
        {
            const uint32_t* pa  = &qa.x;
            const uint32_t* pa2 = &qa2.x;
            const uint32_t* pb  = &qb.x;
            const uint32_t* pb2 = &qb2.x;
#pragma unroll
            for (int nt = 0; nt < 4; nt++) {
                d[nt][0]     = pa[nt];  d[nt][1]     = pb[nt];
                d[nt + 4][0] = pa2[nt]; d[nt + 4][1] = pb2[nt];
            }
        }
        uint32_t dl0[2] = {0u, 0u}, dl1[2] = {0u, 0u};

        // ---- gates MMA + merged logits: A LDSM per ks ----
        const uint32_t aAc = hs_base + cur * (HBE * 2) + aA_pat;
#pragma unroll
        for (int ks = 0; ks < 8; ks++) {
            uint32_t A[4];
            LDSM4(A, aAc + ks * 32);
            if (ks < 4) {
#pragma unroll
                for (int nq = 0; nq < 4; nq++) {
                    MMAH16(d[2 * nq],     A, breg[ks][4*nq],   breg[ks][4*nq+1]);
                    MMAH16(d[2 * nq + 1], A, breg[ks][4*nq+2], breg[ks][4*nq+3]);
                }
            } else {
#pragma unroll
                for (int nq = 0; nq < 4; nq++) {
                    uint32_t B[4];
                    LDSM4(B, ABQ(nq) + ks * 32);
                    MMAH16(d[2 * nq],     A, B[0], B[1]);
                    MMAH16(d[2 * nq + 1], A, B[2], B[3]);
                }
            }
            if ((ks >> 1) == l_kq) {   // this warp's logits k-slice
                uint32_t LB[4];
                LDSM4(LB, aBLm + ks * 32);
                MMAH16(dl0, A, LB[0], LB[1]);
                MMAH16(dl1, A, LB[2], LB[3]);
            }
        }
        store_dlog(dl0, dl1, cur);     // logits(h_t) partials -> parity cur

        // ---- independent work while MMAs retire ----
        if (t > 1) ce_pass(nxt, t - 1, t - 2);

        // ---- LSTM cell: thread-local gates, contiguous-u writeback ----
        __half* hn = h_s + nxt * HBE;
        __half2 hhp[4];
#pragma unroll
        for (int p = 0; p < 4; p++) {
            __half2 rif_lo = *(__half2*)&d[2 * p][0];      // (i,f) row gid
            __half2 rif_hi = *(__half2*)&d[2 * p][1];      // (i,f) row gid+8
            __half2 rgo_lo = *(__half2*)&d[2 * p + 1][0];  // (g,o) row gid
            __half2 rgo_hi = *(__half2*)&d[2 * p + 1][1];  // (g,o) row gid+8
            __half2 i2 = __lows2half2(rif_lo, rif_hi);
            __half2 f2 = __highs2half2(rif_lo, rif_hi);
            __half2 g2 = __lows2half2(rgo_lo, rgo_hi);
            __half2 o2 = __highs2half2(rgo_lo, rgo_hi);
            __half2 si = sig2(i2), sf = sig2(f2), so = sig2(o2);
            __half2 tg = tanh2(g2);
            __half2 it = __hmul2(si, tg);
            float c2a = fmaf(__low2float(sf),  cr[2*p],   __low2float(it));
            float c2b = fmaf(__high2float(sf), cr[2*p+1], __high2float(it));
            cr[2*p] = c2a; cr[2*p+1] = c2b;
            hhp[p] = __hmul2(so, tanh2(__floats2half2_rn(c2a, c2b)));
        }
        {
            __half2 lo01 = __lows2half2(hhp[0], hhp[1]);
            __half2 lo23 = __lows2half2(hhp[2], hhp[3]);
            __half2 hi01 = __highs2half2(hhp[0], hhp[1]);
            __half2 hi23 = __highs2half2(hhp[2], hhp[3]);
            uint2 lo = make_uint2(*(uint32_t*)&lo01, *(uint32_t*)&lo23);
            uint2 hi = make_uint2(*(uint32_t*)&hi01, *(uint32_t*)&hi23);
            *(uint2*)&hn[(16 * half + gid) * PITCH + hst_base]     = lo;
            *(uint2*)&hn[(16 * half + gid + 8) * PITCH + hst_base] = hi;
        }
    }

    // ---- tail: logits(h_127) (buffer 1 -> parity 1); consume s=126,127 ----
    barh(bid);
    {
        uint32_t dl0[2] = {0u, 0u}, dl1[2] = {0u, 0u};
        uint32_t aA = hs_base + 1 * (HBE * 2) + aA_pat;
#pragma unroll
        for (int kk = 0; kk < 2; kk++) {
            int ksl = 2 * l_kq + kk;
            uint32_t A[4], LB[4];
            LDSM4(A, aA + ksl * 32);
            LDSM4(LB, aBLm + ksl * 32);
            MMAH16(dl0, A, LB[0], LB[1]);
            MMAH16(dl1, A, LB[2], LB[3]);
        }
        store_dlog(dl0, dl1, 1);
    }
    ce_pass(0, Tc - 2, Tc - 3);   // logits(h_126) in parity 0
    barh(bid);
    ce_pass(1, Tc - 1, Tc - 2);

    // ---- block loss reduction ----
#pragma unroll
    for (int o = 16; o; o >>= 1)
        my_loss += __shfl_xor_sync(0xffffffffu, my_loss, o);
    __shared__ float wsum[16];
    if (lane == 0) wsum[wid] = my_loss;
    __syncthreads();
    if (wid == 0) {
        float v = (lane < 16) ? wsum[lane] : 0.f;
#pragma unroll
        for (int o = 8; o; o >>= 1)
            v += __shfl_xor_sync(0xffffffffu, v, o);
        if (lane == 0) atomicAdd(&d_loss_sum, (double)v);
    }
}

__global__ void finalize_kernel(float* out) {
    out[0] = (float)(d_loss_sum / d_mask_sum);
}

extern "C" void kernel_launch(void* const* d_in, const int* in_sizes, int n_in,
                              void* d_out, int out_size) {
    const int*   inpt  = (const int*)d_in[0];
    const float* h0    = (const float*)d_in[1];
    const float* c0    = (const float*)d_in[2];
    const float* mask  = (const float*)d_in[3];
    // d_in[4] = beta (unused)
    const float* emb   = (const float*)d_in[5];
    const float* W_ih  = (const float*)d_in[6];
    const float* b_ih  = (const float*)d_in[7];
    const float* W_hh  = (const float*)d_in[8];
    const float* b_hh  = (const float*)d_in[9];
    const float* W_lin = (const float*)d_in[10];
    const float* b_lin = (const float*)d_in[11];
    float* out = (float*)d_out;

    cudaFuncSetAttribute(lstm_kernel,
                         cudaFuncAttributeMaxDynamicSharedMemorySize, SM_TOTAL);

    zero_kernel<<<1, 1>>>();
    mask_sum_kernel<<<256, 256>>>(mask, Bc * Tc);
    ew_kernel<<<Vc, NTHR>>>(emb, W_ih, b_ih, b_hh);
    lstm_kernel<<<Bc / NBLK, NTHR, SM_TOTAL>>>(inpt, h0, c0, mask,
                                               W_hh, W_lin, b_lin);
    finalize_kernel<<<1, 1>>>(out);
}